// round 4
// baseline (speedup 1.0000x reference)
#include <cuda_runtime.h>
#include <cuda_fp16.h>
#include <mma.h>
#include <cstdint>

using namespace nvcuda;

#define UN   50000
#define IN_  20000
#define EN   400000
#define UP   50048   // 64-row padded
#define IP   20032

// ---------------- device scratch (no allocations allowed) ----------------
__device__ __align__(16) __half g_Hu[(size_t)UP * 512];   // gathered user emb, fp16
__device__ __align__(16) __half g_Hi[(size_t)IP * 512];   // gathered item emb, fp16
__device__ __align__(16) __half g_Wh[2][512 * 512];       // W_ui, W_iu in fp16
__device__ __align__(16) float  g_Pu[(size_t)UP * 512];   // user_emb @ W_ui  (fs for dir0)
__device__ __align__(16) float  g_Pi[(size_t)IP * 512];   // item_emb @ W_iu  (fs for dir1)
__device__ float  g_Mu[512 * 16];    // user stat proj: cols 0..7 el_ui, 8..15 er_iu
__device__ float  g_Mi[512 * 16];    // item stat proj: cols 0..7 er_ui, 8..15 el_iu
__device__ float  g_uStat[UN * 16];
__device__ float  g_iStat[IN_ * 16];
__device__ float  g_ebuf0[(size_t)EN * 8];  // dir0 logits, then exp()
__device__ float  g_ebuf1[(size_t)EN * 8];  // dir1 logits, then exp()
__device__ float  g_segmax0[IN_ * 8];
__device__ float  g_segsum0[IN_ * 8];
__device__ float  g_segmax1[UN * 8];
__device__ float  g_segsum1[UN * 8];
__device__ float  g_colsum[512];

// ---------------- helpers ----------------
__device__ __forceinline__ void atomicMaxF(float* addr, float val) {
    if (val >= 0.f) atomicMax((int*)addr, __float_as_int(val));
    else            atomicMin((unsigned int*)addr, __float_as_uint(val));
}

__device__ __forceinline__ void red_add_v4(float* p, float4 v) {
    asm volatile("red.global.add.v4.f32 [%0], {%1,%2,%3,%4};"
                 :: "l"(p), "f"(v.x), "f"(v.y), "f"(v.z), "f"(v.w) : "memory");
}

// ---------------- kernels ----------------
// out[:, :512] = b_iu (dir-1 scatter accumulates on top); colsum = 0
__global__ void k_init_out(float* __restrict__ out, const float* __restrict__ b_iu) {
    int idx = blockIdx.x * blockDim.x + threadIdx.x;
    if (idx < UN * 512) {
        int u = idx >> 9, c = idx & 511;
        out[(size_t)u * 1024 + c] = b_iu[c];
    }
    if (idx < 512) g_colsum[idx] = 0.f;
}

__global__ void k_initseg() {
    int idx = blockIdx.x * blockDim.x + threadIdx.x;
    if (idx < IN_ * 8) { g_segmax0[idx] = -1e30f; g_segsum0[idx] = 0.f; }
    if (idx < UN * 8)  { g_segmax1[idx] = -1e30f; g_segsum1[idx] = 0.f; }
}

__global__ void k_convW(const float* __restrict__ Wui, const float* __restrict__ Wiu) {
    int idx = blockIdx.x * blockDim.x + threadIdx.x;
    if (idx < 512 * 512) {
        g_Wh[0][idx] = __float2half(Wui[idx]);
        g_Wh[1][idx] = __float2half(Wiu[idx]);
    }
}

// M matrices: fold (W, attn-vector) into a [512,16] projector per node type
__global__ void k_M(const float* __restrict__ Wui, const float* __restrict__ Wiu,
                    const float* __restrict__ al_ui, const float* __restrict__ ar_ui,
                    const float* __restrict__ al_iu, const float* __restrict__ ar_iu) {
    int idx = blockIdx.x * blockDim.x + threadIdx.x;
    if (idx >= 512 * 16) return;
    int k = idx >> 4, j = idx & 15, h = j & 7;
    const float* W  = (j < 8) ? Wui   : Wiu;
    const float* au = (j < 8) ? al_ui : ar_iu;  // for Mu (users)
    const float* ai = (j < 8) ? ar_ui : al_iu;  // for Mi (items)
    const float* wrow = W + (size_t)k * 512 + h * 64;
    float su = 0.f, si = 0.f;
    #pragma unroll 8
    for (int d = 0; d < 64; d++) {
        float w = wrow[d];
        su += w * au[h * 64 + d];
        si += w * ai[h * 64 + d];
    }
    g_Mu[k * 16 + j] = su;
    g_Mi[k * 16 + j] = si;
}

// gather emb row -> fp16 matrix; also compute the 16 attention stats (fp32)
__global__ void k_stat(const float* __restrict__ emb, const int* __restrict__ gid,
                       int n, int sel) {
    int m = blockIdx.x;
    if (m >= n) return;
    int t = threadIdx.x;  // 128
    __half* H        = sel ? g_Hi    : g_Hu;
    const float* M   = sel ? g_Mi    : g_Mu;
    float* stat      = sel ? g_iStat : g_uStat;

    const float4* x = (const float4*)(emb + (size_t)gid[m] * 512);
    float4 v = x[t];
    __half2* Hrow = (__half2*)(H + (size_t)m * 512);
    Hrow[t * 2]     = __floats2half2_rn(v.x, v.y);
    Hrow[t * 2 + 1] = __floats2half2_rn(v.z, v.w);

    float acc[16];
    #pragma unroll
    for (int j = 0; j < 16; j++) acc[j] = 0.f;
    float xv[4] = {v.x, v.y, v.z, v.w};
    #pragma unroll
    for (int q = 0; q < 4; q++) {
        const float* Mr = M + (t * 4 + q) * 16;
        #pragma unroll
        for (int j = 0; j < 16; j++) acc[j] += xv[q] * Mr[j];
    }
    __shared__ float red[128 * 16];
    #pragma unroll
    for (int j = 0; j < 16; j++) red[t * 16 + j] = acc[j];
    __syncthreads();
    for (int s = 64; s >= 1; s >>= 1) {
        if (t < s) {
            #pragma unroll
            for (int j = 0; j < 16; j++) red[t * 16 + j] += red[(t + s) * 16 + j];
        }
        __syncthreads();
    }
    if (t < 16) stat[m * 16 + t] = red[t];
}

// fp16 GEMM  C[M,512] = A[M,512] @ B[512,512], wmma 16x16x16, fp32 accum
#define BM 64
#define BN 128
__global__ void k_gemm(int sel) {
    const __half* A = sel ? g_Hi : g_Hu;
    const __half* B = g_Wh[sel];
    float* C        = sel ? g_Pi : g_Pu;

    __shared__ __align__(16) __half As[BM][24];
    __shared__ __align__(16) __half Bs[16][136];

    int m0 = blockIdx.x * BM, n0 = blockIdx.y * BN;
    int tid = threadIdx.x;                 // 256
    int warp = tid >> 5;
    int wm = warp >> 2, wn = warp & 3;     // 2 x 4 warps, 32x32 per warp

    wmma::fragment<wmma::accumulator, 16, 16, 16, float> acc[2][2];
    #pragma unroll
    for (int i = 0; i < 2; i++)
        #pragma unroll
        for (int j = 0; j < 2; j++) wmma::fill_fragment(acc[i][j], 0.f);

    for (int k0 = 0; k0 < 512; k0 += 16) {
        {   // A tile 64x16
            int row = tid >> 2, col = (tid & 3) * 4;
            *(uint2*)&As[row][col] =
                *(const uint2*)(A + (size_t)(m0 + row) * 512 + k0 + col);
        }
        {   // B tile 16x128
            int row = tid >> 4, col = (tid & 15) * 8;
            *(uint4*)&Bs[row][col] =
                *(const uint4*)(B + (size_t)(k0 + row) * 512 + n0 + col);
        }
        __syncthreads();
        wmma::fragment<wmma::matrix_a, 16, 16, 16, __half, wmma::row_major> af[2];
        wmma::fragment<wmma::matrix_b, 16, 16, 16, __half, wmma::row_major> bf[2];
        #pragma unroll
        for (int i = 0; i < 2; i++) wmma::load_matrix_sync(af[i], &As[wm * 32 + i * 16][0], 24);
        #pragma unroll
        for (int j = 0; j < 2; j++) wmma::load_matrix_sync(bf[j], &Bs[0][wn * 32 + j * 16], 136);
        #pragma unroll
        for (int i = 0; i < 2; i++)
            #pragma unroll
            for (int j = 0; j < 2; j++) wmma::mma_sync(acc[i][j], af[i], bf[j], acc[i][j]);
        __syncthreads();
    }
    #pragma unroll
    for (int i = 0; i < 2; i++)
        #pragma unroll
        for (int j = 0; j < 2; j++)
            wmma::store_matrix_sync(C + (size_t)(m0 + wm * 32 + i * 16) * 512 + n0 + wn * 32 + j * 16,
                                    acc[i][j], 512, wmma::mem_row_major);
}

// logits + segment max.
// dir 0 (u->i): el=uStat[:, 0..7],  er=iStat[:, 0..7],  seg over dst items
// dir 1 (i->u): el=iStat[:, 8..15], er=uStat[:, 8..15], seg over dst users
__global__ void k_edgeA(const int* __restrict__ src, const int* __restrict__ dst, int dir) {
    int idx = blockIdx.x * blockDim.x + threadIdx.x;
    if (idx >= EN * 8) return;
    int e = idx >> 3, h = idx & 7;
    int s = src[e], d = dst[e];
    const float* el = dir ? (g_iStat + 8) : g_uStat;
    const float* er = dir ? (g_uStat + 8) : g_iStat;
    float* ebuf   = dir ? g_ebuf1   : g_ebuf0;
    float* segmax = dir ? g_segmax1 : g_segmax0;
    float v = el[s * 16 + h] + er[d * 16 + h];
    v = v > 0.f ? v : 0.2f * v;          // leaky relu
    ebuf[idx] = v;
    atomicMaxF(&segmax[d * 8 + h], v);
}

// exp + segment sum
__global__ void k_edgeB(const int* __restrict__ dst, int dir) {
    int idx = blockIdx.x * blockDim.x + threadIdx.x;
    if (idx >= EN * 8) return;
    int e = idx >> 3, h = idx & 7;
    int d = dst[e];
    float* ebuf         = dir ? g_ebuf1   : g_ebuf0;
    const float* segmax = dir ? g_segmax1 : g_segmax0;
    float* segsum       = dir ? g_segsum1 : g_segsum0;
    float v = expf(ebuf[idx] - segmax[d * 8 + h]);
    ebuf[idx] = v;
    atomicAdd(&segsum[d * 8 + h], v);
}

// dir 0 (u->i): only the column SUM over all edges is needed (mean-pool fusion)
__global__ void k_msg_mean(const int* __restrict__ src, const int* __restrict__ dst) {
    int t = threadIdx.x;                  // 128, owns cols 4t..4t+3
    int e0 = blockIdx.x * 64;
    int h = t >> 4;
    float4 a = {0.f, 0.f, 0.f, 0.f};
    #pragma unroll 4
    for (int i = 0; i < 64; i++) {
        int e = e0 + i;
        int s = src[e], d = dst[e];
        float alpha = g_ebuf0[e * 8 + h] / g_segsum0[d * 8 + h];
        float4 p = ((const float4*)(g_Pu + (size_t)s * 512))[t];
        a.x += p.x * alpha; a.y += p.y * alpha; a.z += p.z * alpha; a.w += p.w * alpha;
    }
    red_add_v4(&g_colsum[t * 4], a);
}

// dir 1 (i->u): scatter-add straight into out[:, 0:512] (pre-initialized with b_iu)
__global__ void k_msg_scatter(const int* __restrict__ src, const int* __restrict__ dst,
                              float* __restrict__ out) {
    int tid = threadIdx.x;                // 256 = 2 edges x 128 lanes
    int e = blockIdx.x * 2 + (tid >> 7);
    int t = tid & 127;
    int h = t >> 4;
    int s = src[e], d = dst[e];
    float alpha = g_ebuf1[e * 8 + h] / g_segsum1[d * 8 + h];
    float4 p = ((const float4*)(g_Pi + (size_t)s * 512))[t];
    float4 v = {p.x * alpha, p.y * alpha, p.z * alpha, p.w * alpha};
    red_add_v4(out + (size_t)d * 1024 + t * 4, v);
}

// out[:, 512:1024] = colsum / I + b_ui
__global__ void k_final(float* __restrict__ out, const float* __restrict__ b_ui) {
    int idx = blockIdx.x * blockDim.x + threadIdx.x;
    if (idx >= UN * 512) return;
    int u = idx >> 9, c = idx & 511;
    out[(size_t)u * 1024 + 512 + c] = g_colsum[c] * (1.f / IN_) + b_ui[c];
}

// ---------------- launch ----------------
extern "C" void kernel_launch(void* const* d_in, const int* in_sizes, int n_in,
                              void* d_out, int out_size) {
    (void)in_sizes; (void)n_in; (void)out_size;
    const int*   u_gid    = (const int*)  d_in[0];
    const int*   i_gid    = (const int*)  d_in[1];
    const int*   src_u    = (const int*)  d_in[2];
    const int*   dst_i    = (const int*)  d_in[3];
    const float* user_emb = (const float*)d_in[4];
    const float* item_emb = (const float*)d_in[5];
    const float* W_ui     = (const float*)d_in[6];
    const float* al_ui    = (const float*)d_in[7];
    const float* ar_ui    = (const float*)d_in[8];
    const float* b_ui     = (const float*)d_in[9];
    const float* W_iu     = (const float*)d_in[10];
    const float* al_iu    = (const float*)d_in[11];
    const float* ar_iu    = (const float*)d_in[12];
    const float* b_iu     = (const float*)d_in[13];
    float* out = (float*)d_out;

    k_init_out<<<(UN * 512 + 255) / 256, 256>>>(out, b_iu);
    k_initseg<<<(UN * 8 + 255) / 256, 256>>>();
    k_convW<<<(512 * 512 + 255) / 256, 256>>>(W_ui, W_iu);
    k_M<<<(512 * 16 + 255) / 256, 256>>>(W_ui, W_iu, al_ui, ar_ui, al_iu, ar_iu);
    k_stat<<<UN, 128>>>(user_emb, u_gid, UN, 0);
    k_stat<<<IN_, 128>>>(item_emb, i_gid, IN_, 1);
    k_gemm<<<dim3(UP / BM, 512 / BN), 256>>>(0);
    k_gemm<<<dim3(IP / BM, 512 / BN), 256>>>(1);

    // direction 0: user -> item (only column-mean of result needed)
    k_edgeA<<<(EN * 8 + 255) / 256, 256>>>(src_u, dst_i, 0);
    k_edgeB<<<(EN * 8 + 255) / 256, 256>>>(dst_i, 0);
    k_msg_mean<<<EN / 64, 128>>>(src_u, dst_i);

    // direction 1: item -> user (scatter into out[:, :512])
    k_edgeA<<<(EN * 8 + 255) / 256, 256>>>(dst_i, src_u, 1);
    k_edgeB<<<(EN * 8 + 255) / 256, 256>>>(src_u, 1);
    k_msg_scatter<<<EN / 2, 256>>>(dst_i, src_u, out);

    k_final<<<(UN * 512 + 255) / 256, 256>>>(out, b_ui);
}

// round 5
// speedup vs baseline: 1.0978x; 1.0978x over previous
#include <cuda_runtime.h>
#include <cuda_fp16.h>
#include <mma.h>
#include <cstdint>

using namespace nvcuda;

#define UN   50000
#define IN_  20000
#define EN   400000
#define UP   50048   // 128-row padded
#define IP   20096   // 128-row padded

// ---------------- device scratch (no allocations allowed; BSS zero-init) ----
__device__ __align__(16) __half g_Hu[(size_t)UP * 512];
__device__ __align__(16) __half g_Hi[(size_t)IP * 512];
__device__ __align__(16) __half g_Wh[2][512 * 512];
__device__ __align__(16) float  g_Pu[(size_t)UP * 512];
__device__ __align__(16) float  g_Pi[(size_t)IP * 512];
__device__ float  g_Mu[512 * 16];
__device__ float  g_Mi[512 * 16];
__device__ float  g_uStat[UN * 16];
__device__ float  g_iStat[IN_ * 16];
__device__ float  g_ebuf0[(size_t)EN * 8];  // dir0 exp(logit)
__device__ float  g_ebuf1[(size_t)EN * 8];  // dir1 exp(logit)
__device__ float  g_segsum0[IN_ * 8];
__device__ float  g_segsum1[UN * 8];
__device__ float  g_wsum[UN * 8];           // dir0: sum of alpha per (src user, head)
__device__ float  g_colsum[512];
__device__ int    g_deg[UN];
__device__ int    g_cursor[UN];
__device__ int    g_off[UN + 1];
__device__ int    g_eidx[EN];
__device__ int    g_esrc[EN];

// ---------------- helpers ----------------
__device__ __forceinline__ void red_add_v4(float* p, float4 v) {
    asm volatile("red.global.add.v4.f32 [%0], {%1,%2,%3,%4};"
                 :: "l"(p), "f"(v.x), "f"(v.y), "f"(v.z), "f"(v.w) : "memory");
}
__device__ __forceinline__ void cp_async16(void* s, const void* g) {
    asm volatile("cp.async.cg.shared.global [%0], [%1], 16;"
                 :: "r"((unsigned)__cvta_generic_to_shared(s)), "l"(g));
}
#define CP_COMMIT() asm volatile("cp.async.commit_group;")
#define CP_WAIT(n)  asm volatile("cp.async.wait_group %0;" :: "n"(n))

// ---------------- kernels ----------------
__global__ void k_zero() {
    int idx = blockIdx.x * blockDim.x + threadIdx.x;
    if (idx < UN * 8) { g_segsum1[idx] = 0.f; g_wsum[idx] = 0.f; }
    if (idx < IN_ * 8) g_segsum0[idx] = 0.f;
    if (idx < UN) { g_deg[idx] = 0; g_cursor[idx] = 0; }
    if (idx < 512) g_colsum[idx] = 0.f;
}

__global__ void k_convW(const float* __restrict__ Wui, const float* __restrict__ Wiu) {
    int idx = blockIdx.x * blockDim.x + threadIdx.x;
    if (idx < 512 * 512) {
        g_Wh[0][idx] = __float2half(Wui[idx]);
        g_Wh[1][idx] = __float2half(Wiu[idx]);
    }
}

// fold (W, attn) into [512,16] projectors per node type
__global__ void k_M(const float* __restrict__ Wui, const float* __restrict__ Wiu,
                    const float* __restrict__ al_ui, const float* __restrict__ ar_ui,
                    const float* __restrict__ al_iu, const float* __restrict__ ar_iu) {
    int idx = blockIdx.x * blockDim.x + threadIdx.x;
    if (idx >= 512 * 16) return;
    int k = idx >> 4, j = idx & 15, h = j & 7;
    const float* W  = (j < 8) ? Wui   : Wiu;
    const float* au = (j < 8) ? al_ui : ar_iu;  // users
    const float* ai = (j < 8) ? ar_ui : al_iu;  // items
    const float4* wrow = (const float4*)(W + (size_t)k * 512 + h * 64);
    const float4* auv  = (const float4*)(au + h * 64);
    const float4* aiv  = (const float4*)(ai + h * 64);
    float su = 0.f, si = 0.f;
    #pragma unroll
    for (int q = 0; q < 16; q++) {
        float4 w = wrow[q], a = auv[q], b = aiv[q];
        su += w.x * a.x + w.y * a.y + w.z * a.z + w.w * a.w;
        si += w.x * b.x + w.y * b.y + w.z * b.z + w.w * b.w;
    }
    g_Mu[k * 16 + j] = su;
    g_Mi[k * 16 + j] = si;
}

// gather row -> fp16, compute 16 attention stats
__global__ void k_stat(const float* __restrict__ emb, const int* __restrict__ gid,
                       int n, int sel) {
    int m = blockIdx.x;
    if (m >= n) return;
    int t = threadIdx.x;  // 128
    __half* H      = sel ? g_Hi    : g_Hu;
    const float* M = sel ? g_Mi    : g_Mu;
    float* stat    = sel ? g_iStat : g_uStat;

    const float4* x = (const float4*)(emb + (size_t)gid[m] * 512);
    float4 v = x[t];
    __half2* Hrow = (__half2*)(H + (size_t)m * 512);
    Hrow[t * 2]     = __floats2half2_rn(v.x, v.y);
    Hrow[t * 2 + 1] = __floats2half2_rn(v.z, v.w);

    float acc[16];
    #pragma unroll
    for (int j = 0; j < 16; j++) acc[j] = 0.f;
    float xv[4] = {v.x, v.y, v.z, v.w};
    #pragma unroll
    for (int q = 0; q < 4; q++) {
        const float* Mr = M + (t * 4 + q) * 16;
        #pragma unroll
        for (int j = 0; j < 16; j++) acc[j] += xv[q] * Mr[j];
    }
    __shared__ float red[128 * 16];
    #pragma unroll
    for (int j = 0; j < 16; j++) red[t * 16 + j] = acc[j];
    __syncthreads();
    for (int s = 64; s >= 1; s >>= 1) {
        if (t < s) {
            #pragma unroll
            for (int j = 0; j < 16; j++) red[t * 16 + j] += red[(t + s) * 16 + j];
        }
        __syncthreads();
    }
    if (t < 16) stat[m * 16 + t] = red[t];
}

// fp16 GEMM  C[M,512] = A[M,512] @ B[512,512]; BM=128 BN=64 BK=32, cp.async 2-stage
__global__ void __launch_bounds__(256) k_gemm(int sel) {
    const __half* A = sel ? g_Hi : g_Hu;
    const __half* B = g_Wh[sel];
    float* C        = sel ? g_Pi : g_Pu;

    __shared__ __align__(16) __half As[2][128][40];
    __shared__ __align__(16) __half Bs[2][32][72];

    int m0 = blockIdx.x * 128, n0 = blockIdx.y * 64;
    int tid = threadIdx.x;
    int warp = tid >> 5;
    int wm = warp >> 1, wn = warp & 1;     // 4x2 warps, 32x32 each

    wmma::fragment<wmma::accumulator, 16, 16, 16, float> acc[2][2];
    #pragma unroll
    for (int i = 0; i < 2; i++)
        #pragma unroll
        for (int j = 0; j < 2; j++) wmma::fill_fragment(acc[i][j], 0.f);

    // A stage: 128x32 halves = 512 v16 (2/thread). B stage: 32x64 = 256 v16 (1/thread)
    int ar0 = tid >> 1, ac0 = (tid & 1) * 16;          // 2 rows-halves pattern: v = tid*2+r
    (void)ar0; (void)ac0;

    auto load_stage = [&](int st, int k0) {
        #pragma unroll
        for (int r = 0; r < 2; r++) {
            int v = tid * 2 + r;
            int row = v >> 2, col = (v & 3) * 8;
            cp_async16(&As[st][row][col], A + (size_t)(m0 + row) * 512 + k0 + col);
        }
        int brow = tid >> 3, bcol = (tid & 7) * 8;
        cp_async16(&Bs[st][brow][bcol], B + (size_t)(k0 + brow) * 512 + n0 + bcol);
    };

    load_stage(0, 0);
    CP_COMMIT();

    for (int k = 0; k < 16; k++) {
        if (k < 15) {
            load_stage((k + 1) & 1, (k + 1) * 32);
            CP_COMMIT();
            CP_WAIT(1);
        } else {
            CP_WAIT(0);
        }
        __syncthreads();
        int st = k & 1;
        #pragma unroll
        for (int ks = 0; ks < 2; ks++) {
            wmma::fragment<wmma::matrix_a, 16, 16, 16, __half, wmma::row_major> af[2];
            wmma::fragment<wmma::matrix_b, 16, 16, 16, __half, wmma::row_major> bf[2];
            #pragma unroll
            for (int i = 0; i < 2; i++)
                wmma::load_matrix_sync(af[i], &As[st][wm * 32 + i * 16][ks * 16], 40);
            #pragma unroll
            for (int j = 0; j < 2; j++)
                wmma::load_matrix_sync(bf[j], &Bs[st][ks * 16][wn * 32 + j * 16], 72);
            #pragma unroll
            for (int i = 0; i < 2; i++)
                #pragma unroll
                for (int j = 0; j < 2; j++)
                    wmma::mma_sync(acc[i][j], af[i], bf[j], acc[i][j]);
        }
        __syncthreads();
    }
    #pragma unroll
    for (int i = 0; i < 2; i++)
        #pragma unroll
        for (int j = 0; j < 2; j++)
            wmma::store_matrix_sync(C + (size_t)(m0 + wm * 32 + i * 16) * 512 + n0 + wn * 32 + j * 16,
                                    acc[i][j], 512, wmma::mem_row_major);
}

// dir0 edges: ex = exp(leakyrelu(el+er)), seg-sum over dst items (no max pass;
// logits are O(0.1) so exp(e)/sum == softmax exactly)
__global__ void k_edge0(const int* __restrict__ src, const int* __restrict__ dst) {
    int idx = blockIdx.x * blockDim.x + threadIdx.x;
    if (idx >= EN * 8) return;
    int e = idx >> 3, h = idx & 7;
    int s = src[e], d = dst[e];
    float v = g_uStat[s * 16 + h] + g_iStat[d * 16 + h];
    v = v > 0.f ? v : 0.2f * v;
    float ex = __expf(v);
    g_ebuf0[idx] = ex;
    atomicAdd(&g_segsum0[d * 8 + h], ex);
}

// dir0: accumulate per-source alpha weights
__global__ void k_wsum(const int* __restrict__ src, const int* __restrict__ dst) {
    int idx = blockIdx.x * blockDim.x + threadIdx.x;
    if (idx >= EN * 8) return;
    int e = idx >> 3, h = idx & 7;
    int s = src[e], d = dst[e];
    float alpha = g_ebuf0[idx] / g_segsum0[d * 8 + h];
    atomicAdd(&g_wsum[s * 8 + h], alpha);
}

// dir0: colsum[c] = sum_u wsum[u,h(c)] * Pu[u,c]   (single pass over Pu)
__global__ void k_colsum() {
    int t = threadIdx.x;          // 128, cols 4t..4t+3
    int h = t >> 4;
    float4 a = {0.f, 0.f, 0.f, 0.f};
    for (int u = blockIdx.x; u < UN; u += gridDim.x) {
        float w = g_wsum[u * 8 + h];
        if (w != 0.f) {
            float4 p = ((const float4*)(g_Pu + (size_t)u * 512))[t];
            a.x += p.x * w; a.y += p.y * w; a.z += p.z * w; a.w += p.w * w;
        }
    }
    red_add_v4(&g_colsum[t * 4], a);
}

// dir1 edges: src=items(dst_i), dst=users(src_u)
__global__ void k_edge1(const int* __restrict__ src_u, const int* __restrict__ dst_i) {
    int idx = blockIdx.x * blockDim.x + threadIdx.x;
    if (idx >= EN * 8) return;
    int e = idx >> 3, h = idx & 7;
    int s = dst_i[e], d = src_u[e];
    float v = g_iStat[s * 16 + 8 + h] + g_uStat[d * 16 + 8 + h];
    v = v > 0.f ? v : 0.2f * v;
    float ex = __expf(v);
    g_ebuf1[idx] = ex;
    atomicAdd(&g_segsum1[d * 8 + h], ex);
}

// CSR build over users
__global__ void k_deg(const int* __restrict__ src_u) {
    int e = blockIdx.x * blockDim.x + threadIdx.x;
    if (e < EN) atomicAdd(&g_deg[src_u[e]], 1);
}

__global__ void k_scan() {   // single block, 1024 threads
    __shared__ int wsums[32];
    __shared__ int carry;
    int t = threadIdx.x, lane = t & 31, w = t >> 5;
    if (t == 0) carry = 0;
    __syncthreads();
    for (int base = 0; base < UN; base += 1024) {
        int i = base + t;
        int v = (i < UN) ? g_deg[i] : 0;
        int x = v;
        #pragma unroll
        for (int o = 1; o < 32; o <<= 1) {
            int y = __shfl_up_sync(0xffffffffu, x, o);
            if (lane >= o) x += y;
        }
        if (lane == 31) wsums[w] = x;
        __syncthreads();
        if (w == 0) {
            int y = wsums[lane];
            #pragma unroll
            for (int o = 1; o < 32; o <<= 1) {
                int z = __shfl_up_sync(0xffffffffu, y, o);
                if (lane >= o) y += z;
            }
            wsums[lane] = y;
        }
        __syncthreads();
        int incl = x + (w > 0 ? wsums[w - 1] : 0) + carry;
        if (i < UN) g_off[i] = incl - v;
        __syncthreads();
        if (t == 1023) carry = incl;
        __syncthreads();
    }
    if (t == 0) g_off[UN] = EN;
}

__global__ void k_fill(const int* __restrict__ src_u, const int* __restrict__ dst_i) {
    int e = blockIdx.x * blockDim.x + threadIdx.x;
    if (e >= EN) return;
    int d = src_u[e];
    int pos = g_off[d] + atomicAdd(&g_cursor[d], 1);
    g_eidx[pos] = e;
    g_esrc[pos] = dst_i[e];
}

// dir1: one block per user — gather its edges, accumulate, write out[:, :512]
__global__ void k_user(float* __restrict__ out, const float* __restrict__ b_iu) {
    int d = blockIdx.x;
    int t = threadIdx.x;      // 128
    int h = t >> 4;
    int off = g_off[d];
    int deg = g_off[d + 1] - off;
    float sinv = 1.f / g_segsum1[d * 8 + h];   // unused if deg==0
    float4 a = {0.f, 0.f, 0.f, 0.f};
    for (int j = 0; j < deg; j++) {
        int e = g_eidx[off + j];
        int s = g_esrc[off + j];
        float alpha = g_ebuf1[e * 8 + h] * sinv;
        float4 p = ((const float4*)(g_Pi + (size_t)s * 512))[t];
        a.x += p.x * alpha; a.y += p.y * alpha; a.z += p.z * alpha; a.w += p.w * alpha;
    }
    float4 b = ((const float4*)b_iu)[t];
    ((float4*)(out + (size_t)d * 1024))[t] =
        make_float4(a.x + b.x, a.y + b.y, a.z + b.z, a.w + b.w);
}

// out[:, 512:1024] = colsum / I + b_ui
__global__ void k_final(float* __restrict__ out, const float* __restrict__ b_ui) {
    int idx = blockIdx.x * blockDim.x + threadIdx.x;
    if (idx >= UN * 512) return;
    int u = idx >> 9, c = idx & 511;
    out[(size_t)u * 1024 + 512 + c] = g_colsum[c] * (1.f / IN_) + b_ui[c];
}

// ---------------- launch ----------------
extern "C" void kernel_launch(void* const* d_in, const int* in_sizes, int n_in,
                              void* d_out, int out_size) {
    (void)in_sizes; (void)n_in; (void)out_size;
    const int*   u_gid    = (const int*)  d_in[0];
    const int*   i_gid    = (const int*)  d_in[1];
    const int*   src_u    = (const int*)  d_in[2];
    const int*   dst_i    = (const int*)  d_in[3];
    const float* user_emb = (const float*)d_in[4];
    const float* item_emb = (const float*)d_in[5];
    const float* W_ui     = (const float*)d_in[6];
    const float* al_ui    = (const float*)d_in[7];
    const float* ar_ui    = (const float*)d_in[8];
    const float* b_ui     = (const float*)d_in[9];
    const float* W_iu     = (const float*)d_in[10];
    const float* al_iu    = (const float*)d_in[11];
    const float* ar_iu    = (const float*)d_in[12];
    const float* b_iu     = (const float*)d_in[13];
    float* out = (float*)d_out;

    k_zero<<<(UN * 8 + 255) / 256, 256>>>();
    k_convW<<<(512 * 512 + 255) / 256, 256>>>(W_ui, W_iu);
    k_M<<<(512 * 16 + 255) / 256, 256>>>(W_ui, W_iu, al_ui, ar_ui, al_iu, ar_iu);
    k_stat<<<UN, 128>>>(user_emb, u_gid, UN, 0);
    k_stat<<<IN_, 128>>>(item_emb, i_gid, IN_, 1);
    k_gemm<<<dim3(UP / 128, 8), 256>>>(0);   // 6th launch -> ncu target
    k_gemm<<<dim3(IP / 128, 8), 256>>>(1);

    // direction 0: user -> item, mean-pool fused to weighted column sum
    k_edge0<<<(EN * 8 + 255) / 256, 256>>>(src_u, dst_i);
    k_wsum<<<(EN * 8 + 255) / 256, 256>>>(src_u, dst_i);
    k_colsum<<<512, 128>>>();

    // direction 1: item -> user via CSR
    k_edge1<<<(EN * 8 + 255) / 256, 256>>>(src_u, dst_i);
    k_deg<<<(EN + 255) / 256, 256>>>(src_u);
    k_scan<<<1, 1024>>>();
    k_fill<<<(EN + 255) / 256, 256>>>(src_u, dst_i);
    k_user<<<UN, 128>>>(out, b_iu);

    k_final<<<(UN * 512 + 255) / 256, 256>>>(out, b_ui);
}

// round 6
// speedup vs baseline: 2.3497x; 2.1404x over previous
#include <cuda_runtime.h>
#include <cuda_fp16.h>
#include <mma.h>
#include <cstdint>

using namespace nvcuda;

#define UN   50000
#define IN_  20000
#define EN   400000
#define UP   50048   // 128-row padded
#define IP   20096   // 128-row padded

// ---------------- device scratch (BSS, no allocations) ----------------
__device__ __align__(16) __half g_Hu[(size_t)UP * 512];
__device__ __align__(16) __half g_Hi[(size_t)IP * 512];
__device__ __align__(16) __half g_Wh[2][512 * 512];
__device__ __align__(16) float  g_Pu[(size_t)UP * 512];
__device__ __align__(16) float  g_Pi[(size_t)IP * 512];
__device__ __align__(16) float  g_Mu[512 * 16];
__device__ __align__(16) float  g_Mi[512 * 16];
__device__ float  g_uStat[UN * 16];
__device__ float  g_iStat[IN_ * 16];
__device__ float  g_ebuf0[(size_t)EN * 8];
__device__ float  g_ebuf1[(size_t)EN * 8];
__device__ float  g_segsum0[IN_ * 8];
__device__ float  g_segsum1[UN * 8];
__device__ float  g_wsum[UN * 8];
__device__ __align__(16) float  g_colsum[512];
__device__ int    g_deg[UN];
__device__ int    g_cursor[UN];
__device__ int    g_off[UN + 1];
__device__ __align__(8) int2 g_epack[EN];   // (ebuf index, src item)

// ---------------- helpers ----------------
__device__ __forceinline__ void red_add_v4(float* p, float4 v) {
    asm volatile("red.global.add.v4.f32 [%0], {%1,%2,%3,%4};"
                 :: "l"(p), "f"(v.x), "f"(v.y), "f"(v.z), "f"(v.w) : "memory");
}
__device__ __forceinline__ void cp_async16(void* s, const void* g) {
    asm volatile("cp.async.cg.shared.global [%0], [%1], 16;"
                 :: "r"((unsigned)__cvta_generic_to_shared(s)), "l"(g));
}
#define CP_COMMIT() asm volatile("cp.async.commit_group;")
#define CP_WAIT(n)  asm volatile("cp.async.wait_group %0;" :: "n"(n))

// ---------------- kernels ----------------
__global__ void k_zero() {
    int idx = blockIdx.x * blockDim.x + threadIdx.x;
    if (idx < UN * 8) { g_segsum1[idx] = 0.f; g_wsum[idx] = 0.f; }
    if (idx < IN_ * 8) g_segsum0[idx] = 0.f;
    if (idx < UN) { g_deg[idx] = 0; g_cursor[idx] = 0; }
    if (idx < 512) g_colsum[idx] = 0.f;
}

__global__ void k_convW(const float* __restrict__ Wui, const float* __restrict__ Wiu) {
    int idx = blockIdx.x * blockDim.x + threadIdx.x;
    if (idx < 512 * 512) {
        g_Wh[0][idx] = __float2half(Wui[idx]);
        g_Wh[1][idx] = __float2half(Wiu[idx]);
    }
}

// fold (W, attn) into [512,16] projectors per node type
__global__ void k_M(const float* __restrict__ Wui, const float* __restrict__ Wiu,
                    const float* __restrict__ al_ui, const float* __restrict__ ar_ui,
                    const float* __restrict__ al_iu, const float* __restrict__ ar_iu) {
    int idx = blockIdx.x * blockDim.x + threadIdx.x;
    if (idx >= 512 * 16) return;
    int k = idx >> 4, j = idx & 15, h = j & 7;
    const float* W  = (j < 8) ? Wui   : Wiu;
    const float* au = (j < 8) ? al_ui : ar_iu;  // users
    const float* ai = (j < 8) ? ar_ui : al_iu;  // items
    const float4* wrow = (const float4*)(W + (size_t)k * 512 + h * 64);
    const float4* auv  = (const float4*)(au + h * 64);
    const float4* aiv  = (const float4*)(ai + h * 64);
    float su = 0.f, si = 0.f;
    #pragma unroll
    for (int q = 0; q < 16; q++) {
        float4 w = wrow[q], a = auv[q], b = aiv[q];
        su += w.x * a.x + w.y * a.y + w.z * a.z + w.w * a.w;
        si += w.x * b.x + w.y * b.y + w.z * b.z + w.w * b.w;
    }
    g_Mu[k * 16 + j] = su;
    g_Mi[k * 16 + j] = si;
}

// warp-per-row: gather emb row -> fp16, 16 attention stats via shfl reduction
__global__ void __launch_bounds__(256) k_stat(const float* __restrict__ emb,
                                              const int* __restrict__ gid,
                                              int n, int sel) {
    int w = threadIdx.x >> 5, lane = threadIdx.x & 31;
    int m = blockIdx.x * 8 + w;
    if (m >= n) return;
    __half* H      = sel ? g_Hi    : g_Hu;
    const float* M = sel ? g_Mi    : g_Mu;
    float* stat    = sel ? g_iStat : g_uStat;

    const float4* x = (const float4*)(emb + (size_t)gid[m] * 512);
    __half2* Hrow = (__half2*)(H + (size_t)m * 512);

    float acc[16];
    #pragma unroll
    for (int j = 0; j < 16; j++) acc[j] = 0.f;

    #pragma unroll
    for (int q = 0; q < 4; q++) {
        int c4 = lane + 32 * q;            // float4 index in row
        float4 v = x[c4];
        Hrow[c4 * 2]     = __floats2half2_rn(v.x, v.y);
        Hrow[c4 * 2 + 1] = __floats2half2_rn(v.z, v.w);
        float xv[4] = {v.x, v.y, v.z, v.w};
        #pragma unroll
        for (int r = 0; r < 4; r++) {
            const float4* Mr = (const float4*)(M + (size_t)(c4 * 4 + r) * 16);
            float4 m0 = Mr[0], m1 = Mr[1], m2 = Mr[2], m3 = Mr[3];
            float xs = xv[r];
            acc[0] += xs * m0.x;  acc[1] += xs * m0.y;  acc[2] += xs * m0.z;  acc[3] += xs * m0.w;
            acc[4] += xs * m1.x;  acc[5] += xs * m1.y;  acc[6] += xs * m1.z;  acc[7] += xs * m1.w;
            acc[8] += xs * m2.x;  acc[9] += xs * m2.y;  acc[10] += xs * m2.z; acc[11] += xs * m2.w;
            acc[12] += xs * m3.x; acc[13] += xs * m3.y; acc[14] += xs * m3.z; acc[15] += xs * m3.w;
        }
    }
    #pragma unroll
    for (int j = 0; j < 16; j++) {
        #pragma unroll
        for (int o = 16; o >= 1; o >>= 1)
            acc[j] += __shfl_xor_sync(0xffffffffu, acc[j], o);
    }
    if (lane < 16) stat[m * 16 + lane] = acc[lane];
}

// fp16 GEMM  C[M,512] = A[M,512] @ B[512,512]; BM=128 BN=64 BK=32, cp.async 2-stage
__global__ void __launch_bounds__(256) k_gemm(int sel) {
    const __half* A = sel ? g_Hi : g_Hu;
    const __half* B = g_Wh[sel];
    float* C        = sel ? g_Pi : g_Pu;

    __shared__ __align__(16) __half As[2][128][40];
    __shared__ __align__(16) __half Bs[2][32][72];

    int m0 = blockIdx.x * 128, n0 = blockIdx.y * 64;
    int tid = threadIdx.x;
    int warp = tid >> 5;
    int wm = warp >> 1, wn = warp & 1;     // 4x2 warps, 32x32 each

    wmma::fragment<wmma::accumulator, 16, 16, 16, float> acc[2][2];
    #pragma unroll
    for (int i = 0; i < 2; i++)
        #pragma unroll
        for (int j = 0; j < 2; j++) wmma::fill_fragment(acc[i][j], 0.f);

    auto load_stage = [&](int st, int k0) {
        #pragma unroll
        for (int r = 0; r < 2; r++) {
            int v = tid * 2 + r;
            int row = v >> 2, col = (v & 3) * 8;
            cp_async16(&As[st][row][col], A + (size_t)(m0 + row) * 512 + k0 + col);
        }
        int brow = tid >> 3, bcol = (tid & 7) * 8;
        cp_async16(&Bs[st][brow][bcol], B + (size_t)(k0 + brow) * 512 + n0 + bcol);
    };

    load_stage(0, 0);
    CP_COMMIT();

    for (int k = 0; k < 16; k++) {
        if (k < 15) {
            load_stage((k + 1) & 1, (k + 1) * 32);
            CP_COMMIT();
            CP_WAIT(1);
        } else {
            CP_WAIT(0);
        }
        __syncthreads();
        int st = k & 1;
        #pragma unroll
        for (int ks = 0; ks < 2; ks++) {
            wmma::fragment<wmma::matrix_a, 16, 16, 16, __half, wmma::row_major> af[2];
            wmma::fragment<wmma::matrix_b, 16, 16, 16, __half, wmma::row_major> bf[2];
            #pragma unroll
            for (int i = 0; i < 2; i++)
                wmma::load_matrix_sync(af[i], &As[st][wm * 32 + i * 16][ks * 16], 40);
            #pragma unroll
            for (int j = 0; j < 2; j++)
                wmma::load_matrix_sync(bf[j], &Bs[st][ks * 16][wn * 32 + j * 16], 72);
            #pragma unroll
            for (int i = 0; i < 2; i++)
                #pragma unroll
                for (int j = 0; j < 2; j++)
                    wmma::mma_sync(acc[i][j], af[i], bf[j], acc[i][j]);
        }
        __syncthreads();
    }
    #pragma unroll
    for (int i = 0; i < 2; i++)
        #pragma unroll
        for (int j = 0; j < 2; j++)
            wmma::store_matrix_sync(C + (size_t)(m0 + wm * 32 + i * 16) * 512 + n0 + wn * 32 + j * 16,
                                    acc[i][j], 512, wmma::mem_row_major);
}

// both directions fused: exp(leakyrelu(logit)), seg-sums, user degree.
// (logits are O(0.1): exp is safe without max subtraction — exact softmax)
__global__ void k_edge_all(const int* __restrict__ src_u, const int* __restrict__ dst_i) {
    int idx = blockIdx.x * blockDim.x + threadIdx.x;
    if (idx >= EN * 8) return;
    int e = idx >> 3, h = idx & 7;
    int su = src_u[e], di = dst_i[e];
    // dir0: user su -> item di
    float v0 = g_uStat[su * 16 + h] + g_iStat[di * 16 + h];
    v0 = v0 > 0.f ? v0 : 0.2f * v0;
    float ex0 = __expf(v0);
    g_ebuf0[idx] = ex0;
    atomicAdd(&g_segsum0[di * 8 + h], ex0);
    // dir1: item di -> user su
    float v1 = g_iStat[di * 16 + 8 + h] + g_uStat[su * 16 + 8 + h];
    v1 = v1 > 0.f ? v1 : 0.2f * v1;
    float ex1 = __expf(v1);
    g_ebuf1[idx] = ex1;
    atomicAdd(&g_segsum1[su * 8 + h], ex1);
    if (h == 0) atomicAdd(&g_deg[su], 1);
}

// dir0: per-source alpha weight accumulation
__global__ void k_wsum(const int* __restrict__ src_u, const int* __restrict__ dst_i) {
    int idx = blockIdx.x * blockDim.x + threadIdx.x;
    if (idx >= EN * 8) return;
    int e = idx >> 3, h = idx & 7;
    int s = src_u[e], d = dst_i[e];
    float alpha = g_ebuf0[idx] / g_segsum0[d * 8 + h];
    atomicAdd(&g_wsum[s * 8 + h], alpha);
}

// dir0: colsum[c] = sum_u wsum[u,h(c)] * Pu[u,c]
__global__ void k_colsum() {
    int t = threadIdx.x;          // 128, cols 4t..4t+3
    int h = t >> 4;
    float4 a = {0.f, 0.f, 0.f, 0.f};
    for (int u = blockIdx.x; u < UN; u += gridDim.x) {
        float w = g_wsum[u * 8 + h];
        if (w != 0.f) {
            float4 p = ((const float4*)(g_Pu + (size_t)u * 512))[t];
            a.x += p.x * w; a.y += p.y * w; a.z += p.z * w; a.w += p.w * w;
        }
    }
    red_add_v4(&g_colsum[t * 4], a);
}

__global__ void k_scan() {   // single block, 1024 threads: exclusive scan of deg
    __shared__ int wsums[32];
    __shared__ int carry;
    int t = threadIdx.x, lane = t & 31, w = t >> 5;
    if (t == 0) carry = 0;
    __syncthreads();
    for (int base = 0; base < UN; base += 1024) {
        int i = base + t;
        int v = (i < UN) ? g_deg[i] : 0;
        int x = v;
        #pragma unroll
        for (int o = 1; o < 32; o <<= 1) {
            int y = __shfl_up_sync(0xffffffffu, x, o);
            if (lane >= o) x += y;
        }
        if (lane == 31) wsums[w] = x;
        __syncthreads();
        if (w == 0) {
            int y = wsums[lane];
            #pragma unroll
            for (int o = 1; o < 32; o <<= 1) {
                int z = __shfl_up_sync(0xffffffffu, y, o);
                if (lane >= o) y += z;
            }
            wsums[lane] = y;
        }
        __syncthreads();
        int incl = x + (w > 0 ? wsums[w - 1] : 0) + carry;
        if (i < UN) g_off[i] = incl - v;
        __syncthreads();
        if (t == 1023) carry = incl;
        __syncthreads();
    }
    if (t == 0) g_off[UN] = EN;
}

__global__ void k_fill(const int* __restrict__ src_u, const int* __restrict__ dst_i) {
    int e = blockIdx.x * blockDim.x + threadIdx.x;
    if (e >= EN) return;
    int d = src_u[e];
    int pos = g_off[d] + atomicAdd(&g_cursor[d], 1);
    g_epack[pos] = make_int2(e, dst_i[e]);
}

// dir1 + final: one block per user; write full 1024-wide output row
__global__ void __launch_bounds__(128) k_user(float* __restrict__ out,
                                              const float* __restrict__ b_iu,
                                              const float* __restrict__ b_ui) {
    int d = blockIdx.x;
    int t = threadIdx.x;      // 128
    int h = t >> 4;
    int off = g_off[d];
    int deg = g_off[d + 1] - off;
    float sinv = 1.f / g_segsum1[d * 8 + h];
    float4 a = {0.f, 0.f, 0.f, 0.f};
    int j = 0;
    for (; j + 2 <= deg; j += 2) {
        int2 p0 = g_epack[off + j], p1 = g_epack[off + j + 1];
        float w0 = g_ebuf1[(size_t)p0.x * 8 + h] * sinv;
        float w1 = g_ebuf1[(size_t)p1.x * 8 + h] * sinv;
        float4 q0 = ((const float4*)(g_Pi + (size_t)p0.y * 512))[t];
        float4 q1 = ((const float4*)(g_Pi + (size_t)p1.y * 512))[t];
        a.x += q0.x * w0 + q1.x * w1;
        a.y += q0.y * w0 + q1.y * w1;
        a.z += q0.z * w0 + q1.z * w1;
        a.w += q0.w * w0 + q1.w * w1;
    }
    if (j < deg) {
        int2 p0 = g_epack[off + j];
        float w0 = g_ebuf1[(size_t)p0.x * 8 + h] * sinv;
        float4 q0 = ((const float4*)(g_Pi + (size_t)p0.y * 512))[t];
        a.x += q0.x * w0; a.y += q0.y * w0; a.z += q0.z * w0; a.w += q0.w * w0;
    }
    float4 b0 = ((const float4*)b_iu)[t];
    ((float4*)(out + (size_t)d * 1024))[t] =
        make_float4(a.x + b0.x, a.y + b0.y, a.z + b0.z, a.w + b0.w);
    float4 cs = ((const float4*)g_colsum)[t];
    float4 b1 = ((const float4*)b_ui)[t];
    const float inv = 1.f / IN_;
    ((float4*)(out + (size_t)d * 1024 + 512))[t] =
        make_float4(cs.x * inv + b1.x, cs.y * inv + b1.y,
                    cs.z * inv + b1.z, cs.w * inv + b1.w);
}

// ---------------- launch ----------------
extern "C" void kernel_launch(void* const* d_in, const int* in_sizes, int n_in,
                              void* d_out, int out_size) {
    (void)in_sizes; (void)n_in; (void)out_size;
    const int*   u_gid    = (const int*)  d_in[0];
    const int*   i_gid    = (const int*)  d_in[1];
    const int*   src_u    = (const int*)  d_in[2];
    const int*   dst_i    = (const int*)  d_in[3];
    const float* user_emb = (const float*)d_in[4];
    const float* item_emb = (const float*)d_in[5];
    const float* W_ui     = (const float*)d_in[6];
    const float* al_ui    = (const float*)d_in[7];
    const float* ar_ui    = (const float*)d_in[8];
    const float* b_ui     = (const float*)d_in[9];
    const float* W_iu     = (const float*)d_in[10];
    const float* al_iu    = (const float*)d_in[11];
    const float* ar_iu    = (const float*)d_in[12];
    const float* b_iu     = (const float*)d_in[13];
    float* out = (float*)d_out;

    k_convW<<<(512 * 512 + 255) / 256, 256>>>(W_ui, W_iu);                       // 1
    k_M<<<(512 * 16 + 255) / 256, 256>>>(W_ui, W_iu, al_ui, ar_ui, al_iu, ar_iu);// 2
    k_stat<<<(UN + 7) / 8, 256>>>(user_emb, u_gid, UN, 0);                       // 3
    k_gemm<<<dim3(UP / 128, 8), 256>>>(0);                                       // 4 <- ncu slot
    k_stat<<<(IN_ + 7) / 8, 256>>>(item_emb, i_gid, IN_, 1);                     // 5
    k_gemm<<<dim3(IP / 128, 8), 256>>>(1);                                       // 6
    k_zero<<<(UN * 8 + 255) / 256, 256>>>();                                     // 7
    k_edge_all<<<(EN * 8 + 255) / 256, 256>>>(src_u, dst_i);                     // 8
    k_wsum<<<(EN * 8 + 255) / 256, 256>>>(src_u, dst_i);                         // 9
    k_colsum<<<512, 128>>>();                                                    // 10
    k_scan<<<1, 1024>>>();                                                       // 11
    k_fill<<<(EN + 255) / 256, 256>>>(src_u, dst_i);                             // 12
    k_user<<<UN, 128>>>(out, b_iu, b_ui);                                        // 13
}

// round 9
// speedup vs baseline: 3.9691x; 1.6892x over previous
#include <cuda_runtime.h>
#include <cuda_fp16.h>
#include <mma.h>
#include <cstdint>

using namespace nvcuda;

#define UN   50000
#define IN_  20000
#define EN   400000
#define UP   50048   // 128-row padded
#define IP   20096   // 128-row padded

// ---------------- device scratch (BSS, no allocations) ----------------
__device__ __align__(16) __half g_Hu[(size_t)UP * 512];
__device__ __align__(16) __half g_Hi[(size_t)IP * 512];
__device__ __align__(16) __half g_Wh[512 * 512];          // W_iu fp16 (only GEMM left)
__device__ __align__(16) float  g_Pi[(size_t)IP * 512];
__device__ __align__(16) float  g_Mu[512 * 16];
__device__ __align__(16) float  g_Mi[512 * 16];
__device__ float  g_uStat[UN * 16];
__device__ float  g_iStat[IN_ * 16];
__device__ float  g_ebuf1[(size_t)EN * 8];
__device__ float  g_segsum0[IN_ * 8];
__device__ float  g_segsum1[UN * 8];
__device__ float  g_wsum[UN * 8];
__device__ float  g_T[8 * 512];             // T[h][k] = sum_u wsum[u,h]*Hu[u,k]
__device__ __align__(16) float  g_colsum[512];
__device__ int    g_deg[UN];
__device__ int    g_cursor[UN];
__device__ int    g_off[UN + 1];
__device__ __align__(8) int2 g_epack[EN];   // (edge id, src item)

// ---------------- helpers ----------------
__device__ __forceinline__ void cp_async16(void* s, const void* g) {
    asm volatile("cp.async.cg.shared.global [%0], [%1], 16;"
                 :: "r"((unsigned)__cvta_generic_to_shared(s)), "l"(g));
}
#define CP_COMMIT() asm volatile("cp.async.commit_group;")
#define CP_WAIT(n)  asm volatile("cp.async.wait_group %0;" :: "n"(n))

// ---------------- kernels ----------------
__global__ void k_zero() {
    int idx = blockIdx.x * blockDim.x + threadIdx.x;
    if (idx < UN * 8) { g_segsum1[idx] = 0.f; g_wsum[idx] = 0.f; }
    if (idx < IN_ * 8) g_segsum0[idx] = 0.f;
    if (idx < UN) { g_deg[idx] = 0; g_cursor[idx] = 0; }
    if (idx < 8 * 512) g_T[idx] = 0.f;
}

// Wh = fp16(W_iu);  fold (W, attn) into [512,16] projectors
__global__ void k_prep(const float* __restrict__ Wui, const float* __restrict__ Wiu,
                       const float* __restrict__ al_ui, const float* __restrict__ ar_ui,
                       const float* __restrict__ al_iu, const float* __restrict__ ar_iu) {
    int idx = blockIdx.x * blockDim.x + threadIdx.x;
    if (idx < 512 * 512) g_Wh[idx] = __float2half(Wiu[idx]);
    if (idx >= 512 * 16) return;
    int k = idx >> 4, j = idx & 15, h = j & 7;
    const float* W  = (j < 8) ? Wui   : Wiu;
    const float* au = (j < 8) ? al_ui : ar_iu;  // users
    const float* ai = (j < 8) ? ar_ui : al_iu;  // items
    const float4* wrow = (const float4*)(W + (size_t)k * 512 + h * 64);
    const float4* auv  = (const float4*)(au + h * 64);
    const float4* aiv  = (const float4*)(ai + h * 64);
    float su = 0.f, si = 0.f;
    #pragma unroll
    for (int q = 0; q < 16; q++) {
        float4 w = wrow[q], a = auv[q], b = aiv[q];
        su += w.x * a.x + w.y * a.y + w.z * a.z + w.w * a.w;
        si += w.x * b.x + w.y * b.y + w.z * b.z + w.w * b.w;
    }
    g_Mu[k * 16 + j] = su;
    g_Mi[k * 16 + j] = si;
}

// warp-per-row gather->fp16 + 16 attention stats; users and items in one grid
#define UB ((UN + 7) / 8)
#define IB ((IN_ + 7) / 8)
__global__ void __launch_bounds__(256) k_stat(const float* __restrict__ uemb,
                                              const float* __restrict__ iemb,
                                              const int* __restrict__ u_gid,
                                              const int* __restrict__ i_gid) {
    int w = threadIdx.x >> 5, lane = threadIdx.x & 31;
    int sel = (blockIdx.x >= UB);
    int m = (sel ? (blockIdx.x - UB) : blockIdx.x) * 8 + w;
    int n = sel ? IN_ : UN;
    if (m >= n) return;
    const float* emb = sel ? iemb : uemb;
    const int* gid   = sel ? i_gid : u_gid;
    __half* H      = sel ? g_Hi   : g_Hu;
    const float* M = sel ? g_Mi   : g_Mu;
    float* stat    = sel ? g_iStat : g_uStat;

    const float4* x = (const float4*)(emb + (size_t)gid[m] * 512);
    __half2* Hrow = (__half2*)(H + (size_t)m * 512);

    float acc[16];
    #pragma unroll
    for (int j = 0; j < 16; j++) acc[j] = 0.f;

    #pragma unroll
    for (int q = 0; q < 4; q++) {
        int c4 = lane + 32 * q;
        float4 v = x[c4];
        Hrow[c4 * 2]     = __floats2half2_rn(v.x, v.y);
        Hrow[c4 * 2 + 1] = __floats2half2_rn(v.z, v.w);
        float xv[4] = {v.x, v.y, v.z, v.w};
        #pragma unroll
        for (int r = 0; r < 4; r++) {
            const float4* Mr = (const float4*)(M + (size_t)(c4 * 4 + r) * 16);
            float4 m0 = Mr[0], m1 = Mr[1], m2 = Mr[2], m3 = Mr[3];
            float xs = xv[r];
            acc[0] += xs * m0.x;  acc[1] += xs * m0.y;  acc[2] += xs * m0.z;  acc[3] += xs * m0.w;
            acc[4] += xs * m1.x;  acc[5] += xs * m1.y;  acc[6] += xs * m1.z;  acc[7] += xs * m1.w;
            acc[8] += xs * m2.x;  acc[9] += xs * m2.y;  acc[10] += xs * m2.z; acc[11] += xs * m2.w;
            acc[12] += xs * m3.x; acc[13] += xs * m3.y; acc[14] += xs * m3.z; acc[15] += xs * m3.w;
        }
    }
    #pragma unroll
    for (int j = 0; j < 16; j++) {
        #pragma unroll
        for (int o = 16; o >= 1; o >>= 1)
            acc[j] += __shfl_xor_sync(0xffffffffu, acc[j], o);
    }
    if (lane < 16) stat[m * 16 + lane] = acc[lane];
}

// both directions fused: exp(leakyrelu(logit)), seg-sums, user degree
__global__ void k_edge_all(const int* __restrict__ src_u, const int* __restrict__ dst_i) {
    int idx = blockIdx.x * blockDim.x + threadIdx.x;
    if (idx >= EN * 8) return;
    int e = idx >> 3, h = idx & 7;
    int su = src_u[e], di = dst_i[e];
    float v0 = g_uStat[su * 16 + h] + g_iStat[di * 16 + h];
    v0 = v0 > 0.f ? v0 : 0.2f * v0;
    atomicAdd(&g_segsum0[di * 8 + h], __expf(v0));
    float v1 = g_iStat[di * 16 + 8 + h] + g_uStat[su * 16 + 8 + h];
    v1 = v1 > 0.f ? v1 : 0.2f * v1;
    float ex1 = __expf(v1);
    g_ebuf1[idx] = ex1;
    atomicAdd(&g_segsum1[su * 8 + h], ex1);
    if (h == 0) atomicAdd(&g_deg[su], 1);
}

// fp16 GEMM  Pi = Hi @ W_iu; BM=128 BN=64 BK=32, cp.async 2-stage
__global__ void __launch_bounds__(256) k_gemm() {
    const __half* A = g_Hi;
    const __half* B = g_Wh;
    float* C        = g_Pi;

    __shared__ __align__(16) __half As[2][128][40];
    __shared__ __align__(16) __half Bs[2][32][72];

    int m0 = blockIdx.x * 128, n0 = blockIdx.y * 64;
    int tid = threadIdx.x;
    int warp = tid >> 5;
    int wm = warp >> 1, wn = warp & 1;

    wmma::fragment<wmma::accumulator, 16, 16, 16, float> acc[2][2];
    #pragma unroll
    for (int i = 0; i < 2; i++)
        #pragma unroll
        for (int j = 0; j < 2; j++) wmma::fill_fragment(acc[i][j], 0.f);

    auto load_stage = [&](int st, int k0) {
        #pragma unroll
        for (int r = 0; r < 2; r++) {
            int v = tid * 2 + r;
            int row = v >> 2, col = (v & 3) * 8;
            cp_async16(&As[st][row][col], A + (size_t)(m0 + row) * 512 + k0 + col);
        }
        int brow = tid >> 3, bcol = (tid & 7) * 8;
        cp_async16(&Bs[st][brow][bcol], B + (size_t)(k0 + brow) * 512 + n0 + bcol);
    };

    load_stage(0, 0);
    CP_COMMIT();

    for (int k = 0; k < 16; k++) {
        if (k < 15) {
            load_stage((k + 1) & 1, (k + 1) * 32);
            CP_COMMIT();
            CP_WAIT(1);
        } else {
            CP_WAIT(0);
        }
        __syncthreads();
        int st = k & 1;
        #pragma unroll
        for (int ks = 0; ks < 2; ks++) {
            wmma::fragment<wmma::matrix_a, 16, 16, 16, __half, wmma::row_major> af[2];
            wmma::fragment<wmma::matrix_b, 16, 16, 16, __half, wmma::row_major> bf[2];
            #pragma unroll
            for (int i = 0; i < 2; i++)
                wmma::load_matrix_sync(af[i], &As[st][wm * 32 + i * 16][ks * 16], 40);
            #pragma unroll
            for (int j = 0; j < 2; j++)
                wmma::load_matrix_sync(bf[j], &Bs[st][ks * 16][wn * 32 + j * 16], 72);
            #pragma unroll
            for (int i = 0; i < 2; i++)
                #pragma unroll
                for (int j = 0; j < 2; j++)
                    wmma::mma_sync(acc[i][j], af[i], bf[j], acc[i][j]);
        }
        __syncthreads();
    }
    #pragma unroll
    for (int i = 0; i < 2; i++)
        #pragma unroll
        for (int j = 0; j < 2; j++)
            wmma::store_matrix_sync(C + (size_t)(m0 + wm * 32 + i * 16) * 512 + n0 + wn * 32 + j * 16,
                                    acc[i][j], 512, wmma::mem_row_major);
}

// dir0: wsum[u,h] += alpha (recompute exp; ebuf0 not stored)
__global__ void k_wsum(const int* __restrict__ src_u, const int* __restrict__ dst_i) {
    int idx = blockIdx.x * blockDim.x + threadIdx.x;
    if (idx >= EN * 8) return;
    int e = idx >> 3, h = idx & 7;
    int s = src_u[e], d = dst_i[e];
    float v0 = g_uStat[s * 16 + h] + g_iStat[d * 16 + h];
    v0 = v0 > 0.f ? v0 : 0.2f * v0;
    float alpha = __expf(v0) / g_segsum0[d * 8 + h];
    atomicAdd(&g_wsum[s * 8 + h], alpha);
}

// T[h,k] = sum_u wsum[u,h] * Hu[u,k]   (block = 128 users, thread owns 4 k-cols)
__global__ void __launch_bounds__(128) k_T() {
    int t = threadIdx.x;                // owns k = 4t..4t+3
    int u0 = blockIdx.x * 128;
    int nit = (UN - u0 < 128) ? (UN - u0) : 128;
    float acc[8][4];
    #pragma unroll
    for (int h = 0; h < 8; h++)
        #pragma unroll
        for (int q = 0; q < 4; q++) acc[h][q] = 0.f;
    for (int i = 0; i < nit; i++) {
        int u = u0 + i;
        const float4* wp = (const float4*)(g_wsum + (size_t)u * 8);
        float4 wa = wp[0], wb = wp[1];
        float wv[8] = {wa.x, wa.y, wa.z, wa.w, wb.x, wb.y, wb.z, wb.w};
        uint2 hraw = *(const uint2*)(g_Hu + (size_t)u * 512 + t * 4);
        float2 x01 = __half22float2(*(__half2*)&hraw.x);
        float2 x23 = __half22float2(*(__half2*)&hraw.y);
        float xv[4] = {x01.x, x01.y, x23.x, x23.y};
        #pragma unroll
        for (int h = 0; h < 8; h++) {
            float w = wv[h];
            #pragma unroll
            for (int q = 0; q < 4; q++) acc[h][q] += w * xv[q];
        }
    }
    #pragma unroll
    for (int h = 0; h < 8; h++)
        #pragma unroll
        for (int q = 0; q < 4; q++)
            atomicAdd(&g_T[h * 512 + t * 4 + q], acc[h][q]);
}

// colsum[h*64+d] = sum_k T[h,k] * W_ui[k, h*64+d]   (fp32, tiny)
__global__ void __launch_bounds__(64) k_smallgemm(const float* __restrict__ Wui) {
    int h = blockIdx.x, d = threadIdx.x;
    int c = h * 64 + d;
    __shared__ float Ts[512];
    for (int k = d; k < 512; k += 64) Ts[k] = g_T[h * 512 + k];
    __syncthreads();
    float acc = 0.f;
    for (int k = 0; k < 512; k++) acc += Ts[k] * Wui[(size_t)k * 512 + c];
    g_colsum[c] = acc;
}

__global__ void k_scan() {   // single block, 1024 threads: exclusive scan of deg
    __shared__ int wsums[32];
    __shared__ int carry;
    int t = threadIdx.x, lane = t & 31, w = t >> 5;
    if (t == 0) carry = 0;
    __syncthreads();
    for (int base = 0; base < UN; base += 1024) {
        int i = base + t;
        int v = (i < UN) ? g_deg[i] : 0;
        int x = v;
        #pragma unroll
        for (int o = 1; o < 32; o <<= 1) {
            int y = __shfl_up_sync(0xffffffffu, x, o);
            if (lane >= o) x += y;
        }
        if (lane == 31) wsums[w] = x;
        __syncthreads();
        if (w == 0) {
            int y = wsums[lane];
            #pragma unroll
            for (int o = 1; o < 32; o <<= 1) {
                int z = __shfl_up_sync(0xffffffffu, y, o);
                if (lane >= o) y += z;
            }
            wsums[lane] = y;
        }
        __syncthreads();
        int incl = x + (w > 0 ? wsums[w - 1] : 0) + carry;
        if (i < UN) g_off[i] = incl - v;
        __syncthreads();
        if (t == 1023) carry = incl;
        __syncthreads();
    }
    if (t == 0) g_off[UN] = EN;
}

__global__ void k_fill(const int* __restrict__ src_u, const int* __restrict__ dst_i) {
    int e = blockIdx.x * blockDim.x + threadIdx.x;
    if (e >= EN) return;
    int d = src_u[e];
    int pos = g_off[d] + atomicAdd(&g_cursor[d], 1);
    g_epack[pos] = make_int2(e, dst_i[e]);
}

// dir1 + final: one block per user; write full 1024-wide output row
__global__ void __launch_bounds__(128) k_user(float* __restrict__ out,
                                              const float* __restrict__ b_iu,
                                              const float* __restrict__ b_ui) {
    int d = blockIdx.x;
    int t = threadIdx.x;      // 128
    int h = t >> 4;
    int off = g_off[d];
    int deg = g_off[d + 1] - off;
    float sinv = 1.f / g_segsum1[d * 8 + h];
    float4 a = {0.f, 0.f, 0.f, 0.f};
    int j = 0;
    for (; j + 2 <= deg; j += 2) {
        int2 p0 = g_epack[off + j], p1 = g_epack[off + j + 1];
        float w0 = g_ebuf1[(size_t)p0.x * 8 + h] * sinv;
        float w1 = g_ebuf1[(size_t)p1.x * 8 + h] * sinv;
        float4 q0 = ((const float4*)(g_Pi + (size_t)p0.y * 512))[t];
        float4 q1 = ((const float4*)(g_Pi + (size_t)p1.y * 512))[t];
        a.x += q0.x * w0 + q1.x * w1;
        a.y += q0.y * w0 + q1.y * w1;
        a.z += q0.z * w0 + q1.z * w1;
        a.w += q0.w * w0 + q1.w * w1;
    }
    if (j < deg) {
        int2 p0 = g_epack[off + j];
        float w0 = g_ebuf1[(size_t)p0.x * 8 + h] * sinv;
        float4 q0 = ((const float4*)(g_Pi + (size_t)p0.y * 512))[t];
        a.x += q0.x * w0; a.y += q0.y * w0; a.z += q0.z * w0; a.w += q0.w * w0;
    }
    float4 b0 = ((const float4*)b_iu)[t];
    ((float4*)(out + (size_t)d * 1024))[t] =
        make_float4(a.x + b0.x, a.y + b0.y, a.z + b0.z, a.w + b0.w);
    float4 cs = ((const float4*)g_colsum)[t];
    float4 b1 = ((const float4*)b_ui)[t];
    const float inv = 1.f / IN_;
    ((float4*)(out + (size_t)d * 1024 + 512))[t] =
        make_float4(cs.x * inv + b1.x, cs.y * inv + b1.y,
                    cs.z * inv + b1.z, cs.w * inv + b1.w);
}

// ---------------- launch ----------------
extern "C" void kernel_launch(void* const* d_in, const int* in_sizes, int n_in,
                              void* d_out, int out_size) {
    (void)in_sizes; (void)n_in; (void)out_size;
    const int*   u_gid    = (const int*)  d_in[0];
    const int*   i_gid    = (const int*)  d_in[1];
    const int*   src_u    = (const int*)  d_in[2];
    const int*   dst_i    = (const int*)  d_in[3];
    const float* user_emb = (const float*)d_in[4];
    const float* item_emb = (const float*)d_in[5];
    const float* W_ui     = (const float*)d_in[6];
    const float* al_ui    = (const float*)d_in[7];
    const float* ar_ui    = (const float*)d_in[8];
    const float* b_ui     = (const float*)d_in[9];
    const float* W_iu     = (const float*)d_in[10];
    const float* al_iu    = (const float*)d_in[11];
    const float* ar_iu    = (const float*)d_in[12];
    const float* b_iu     = (const float*)d_in[13];
    float* out = (float*)d_out;

    k_zero<<<(UN * 8 + 255) / 256, 256>>>();                                      // 1
    k_prep<<<(512 * 512 + 255) / 256, 256>>>(W_ui, W_iu, al_ui, ar_ui, al_iu, ar_iu); // 2
    k_stat<<<UB + IB, 256>>>(user_emb, item_emb, u_gid, i_gid);                   // 3
    k_edge_all<<<(EN * 8 + 255) / 256, 256>>>(src_u, dst_i);                      // 4 <- ncu slot
    k_gemm<<<dim3(IP / 128, 8), 256>>>();                                         // 5
    k_wsum<<<(EN * 8 + 255) / 256, 256>>>(src_u, dst_i);                          // 6
    k_T<<<(UN + 127) / 128, 128>>>();                                             // 7
    k_smallgemm<<<8, 64>>>(W_ui);                                                 // 8
    k_scan<<<1, 1024>>>();                                                        // 9
    k_fill<<<(EN + 255) / 256, 256>>>(src_u, dst_i);                              // 10
    k_user<<<UN, 128>>>(out, b_iu, b_ui);                                         // 11
}

// round 10
// speedup vs baseline: 4.3442x; 1.0945x over previous
#include <cuda_runtime.h>
#include <cuda_fp16.h>
#include <mma.h>
#include <cstdint>

using namespace nvcuda;

#define UN   50000
#define IN_  20000
#define EN   400000
#define UP   50048   // 128-row padded
#define IP   20096   // 128-row padded

// ---------------- device scratch (BSS, no allocations) ----------------
__device__ __align__(16) __half g_Hu[(size_t)UP * 512];
__device__ __align__(16) __half g_Hi[(size_t)IP * 512];
__device__ __align__(16) __half g_Wh[512 * 512];          // W_iu fp16
__device__ __align__(16) float  g_Pi[(size_t)IP * 512];   // GEMM out fp32
__device__ __align__(16) __half g_Pih[(size_t)IP * 512];  // fp16 copy for gather
__device__ __align__(16) float  g_Mu[512 * 16];
__device__ __align__(16) float  g_Mi[512 * 16];
__device__ float  g_uStat[UN * 16];
__device__ float  g_iStat[IN_ * 16];
__device__ float  g_ebuf1[(size_t)EN * 8];
__device__ float  g_segsum0[IN_ * 8];
__device__ float  g_segsum1[UN * 8];
__device__ float  g_wsum[UN * 8];
__device__ float  g_T[8 * 512];
__device__ float  g_colsum[512];
__device__ int    g_deg[UN];
__device__ int    g_cursor[UN];
__device__ int    g_off[UN];
__device__ int    g_total;
__device__ __align__(8) int2 g_epack[EN];   // (edge id, src item)

// ---------------- helpers ----------------
__device__ __forceinline__ void cp_async16(void* s, const void* g) {
    asm volatile("cp.async.cg.shared.global [%0], [%1], 16;"
                 :: "r"((unsigned)__cvta_generic_to_shared(s)), "l"(g));
}
#define CP_COMMIT() asm volatile("cp.async.commit_group;")
#define CP_WAIT(n)  asm volatile("cp.async.wait_group %0;" :: "n"(n))

// ---------------- kernels ----------------
__global__ void k_zero() {
    int idx = blockIdx.x * blockDim.x + threadIdx.x;
    if (idx < UN * 8) { g_segsum1[idx] = 0.f; g_wsum[idx] = 0.f; }
    if (idx < IN_ * 8) g_segsum0[idx] = 0.f;
    if (idx < UN) { g_deg[idx] = 0; g_cursor[idx] = 0; }
    if (idx < 8 * 512) g_T[idx] = 0.f;
    if (idx < 512) g_colsum[idx] = 0.f;
    if (idx == 0) g_total = 0;
}

// Wh = fp16(W_iu);  fold (W, attn) into [512,16] projectors
__global__ void k_prep(const float* __restrict__ Wui, const float* __restrict__ Wiu,
                       const float* __restrict__ al_ui, const float* __restrict__ ar_ui,
                       const float* __restrict__ al_iu, const float* __restrict__ ar_iu) {
    int idx = blockIdx.x * blockDim.x + threadIdx.x;
    if (idx < 512 * 512) g_Wh[idx] = __float2half(Wiu[idx]);
    if (idx >= 512 * 16) return;
    int k = idx >> 4, j = idx & 15, h = j & 7;
    const float* W  = (j < 8) ? Wui   : Wiu;
    const float* au = (j < 8) ? al_ui : ar_iu;  // users
    const float* ai = (j < 8) ? ar_ui : al_iu;  // items
    const float4* wrow = (const float4*)(W + (size_t)k * 512 + h * 64);
    const float4* auv  = (const float4*)(au + h * 64);
    const float4* aiv  = (const float4*)(ai + h * 64);
    float su = 0.f, si = 0.f;
    #pragma unroll
    for (int q = 0; q < 16; q++) {
        float4 w = wrow[q], a = auv[q], b = aiv[q];
        su += w.x * a.x + w.y * a.y + w.z * a.z + w.w * a.w;
        si += w.x * b.x + w.y * b.y + w.z * b.z + w.w * b.w;
    }
    g_Mu[k * 16 + j] = su;
    g_Mi[k * 16 + j] = si;
}

// warp-per-row gather->fp16 + 16 attention stats; users and items one grid
#define UB ((UN + 7) / 8)
#define IB ((IN_ + 7) / 8)
__global__ void __launch_bounds__(256) k_stat(const float* __restrict__ uemb,
                                              const float* __restrict__ iemb,
                                              const int* __restrict__ u_gid,
                                              const int* __restrict__ i_gid) {
    int w = threadIdx.x >> 5, lane = threadIdx.x & 31;
    int sel = (blockIdx.x >= UB);
    int m = (sel ? (blockIdx.x - UB) : blockIdx.x) * 8 + w;
    int n = sel ? IN_ : UN;
    if (m >= n) return;
    const float* emb = sel ? iemb : uemb;
    const int* gid   = sel ? i_gid : u_gid;
    __half* H      = sel ? g_Hi   : g_Hu;
    const float* M = sel ? g_Mi   : g_Mu;
    float* stat    = sel ? g_iStat : g_uStat;

    const float4* x = (const float4*)(emb + (size_t)gid[m] * 512);
    __half2* Hrow = (__half2*)(H + (size_t)m * 512);

    float acc[16];
    #pragma unroll
    for (int j = 0; j < 16; j++) acc[j] = 0.f;

    #pragma unroll
    for (int q = 0; q < 4; q++) {
        int c4 = lane + 32 * q;
        float4 v = x[c4];
        Hrow[c4 * 2]     = __floats2half2_rn(v.x, v.y);
        Hrow[c4 * 2 + 1] = __floats2half2_rn(v.z, v.w);
        float xv[4] = {v.x, v.y, v.z, v.w};
        #pragma unroll
        for (int r = 0; r < 4; r++) {
            const float4* Mr = (const float4*)(M + (size_t)(c4 * 4 + r) * 16);
            float4 m0 = Mr[0], m1 = Mr[1], m2 = Mr[2], m3 = Mr[3];
            float xs = xv[r];
            acc[0] += xs * m0.x;  acc[1] += xs * m0.y;  acc[2] += xs * m0.z;  acc[3] += xs * m0.w;
            acc[4] += xs * m1.x;  acc[5] += xs * m1.y;  acc[6] += xs * m1.z;  acc[7] += xs * m1.w;
            acc[8] += xs * m2.x;  acc[9] += xs * m2.y;  acc[10] += xs * m2.z; acc[11] += xs * m2.w;
            acc[12] += xs * m3.x; acc[13] += xs * m3.y; acc[14] += xs * m3.z; acc[15] += xs * m3.w;
        }
    }
    #pragma unroll
    for (int j = 0; j < 16; j++) {
        #pragma unroll
        for (int o = 16; o >= 1; o >>= 1)
            acc[j] += __shfl_xor_sync(0xffffffffu, acc[j], o);
    }
    if (lane < 16) stat[m * 16 + lane] = acc[lane];
}

// both directions fused: exp(leakyrelu(logit)), seg-sums, user degree
__global__ void k_edge_all(const int* __restrict__ src_u, const int* __restrict__ dst_i) {
    int idx = blockIdx.x * blockDim.x + threadIdx.x;
    if (idx >= EN * 8) return;
    int e = idx >> 3, h = idx & 7;
    int su = src_u[e], di = dst_i[e];
    float v0 = g_uStat[su * 16 + h] + g_iStat[di * 16 + h];
    v0 = v0 > 0.f ? v0 : 0.2f * v0;
    atomicAdd(&g_segsum0[di * 8 + h], __expf(v0));
    float v1 = g_iStat[di * 16 + 8 + h] + g_uStat[su * 16 + 8 + h];
    v1 = v1 > 0.f ? v1 : 0.2f * v1;
    float ex1 = __expf(v1);
    g_ebuf1[idx] = ex1;
    atomicAdd(&g_segsum1[su * 8 + h], ex1);
    if (h == 0) atomicAdd(&g_deg[su], 1);
}

// fp16 GEMM  Pi = Hi @ W_iu; BM=128 BN=64 BK=32, cp.async 2-stage
__global__ void __launch_bounds__(256) k_gemm() {
    const __half* A = g_Hi;
    const __half* B = g_Wh;
    float* C        = g_Pi;

    __shared__ __align__(16) __half As[2][128][40];
    __shared__ __align__(16) __half Bs[2][32][72];

    int m0 = blockIdx.x * 128, n0 = blockIdx.y * 64;
    int tid = threadIdx.x;
    int warp = tid >> 5;
    int wm = warp >> 1, wn = warp & 1;

    wmma::fragment<wmma::accumulator, 16, 16, 16, float> acc[2][2];
    #pragma unroll
    for (int i = 0; i < 2; i++)
        #pragma unroll
        for (int j = 0; j < 2; j++) wmma::fill_fragment(acc[i][j], 0.f);

    auto load_stage = [&](int st, int k0) {
        #pragma unroll
        for (int r = 0; r < 2; r++) {
            int v = tid * 2 + r;
            int row = v >> 2, col = (v & 3) * 8;
            cp_async16(&As[st][row][col], A + (size_t)(m0 + row) * 512 + k0 + col);
        }
        int brow = tid >> 3, bcol = (tid & 7) * 8;
        cp_async16(&Bs[st][brow][bcol], B + (size_t)(k0 + brow) * 512 + n0 + bcol);
    };

    load_stage(0, 0);
    CP_COMMIT();

    for (int k = 0; k < 16; k++) {
        if (k < 15) {
            load_stage((k + 1) & 1, (k + 1) * 32);
            CP_COMMIT();
            CP_WAIT(1);
        } else {
            CP_WAIT(0);
        }
        __syncthreads();
        int st = k & 1;
        #pragma unroll
        for (int ks = 0; ks < 2; ks++) {
            wmma::fragment<wmma::matrix_a, 16, 16, 16, __half, wmma::row_major> af[2];
            wmma::fragment<wmma::matrix_b, 16, 16, 16, __half, wmma::row_major> bf[2];
            #pragma unroll
            for (int i = 0; i < 2; i++)
                wmma::load_matrix_sync(af[i], &As[st][wm * 32 + i * 16][ks * 16], 40);
            #pragma unroll
            for (int j = 0; j < 2; j++)
                wmma::load_matrix_sync(bf[j], &Bs[st][ks * 16][wn * 32 + j * 16], 72);
            #pragma unroll
            for (int i = 0; i < 2; i++)
                #pragma unroll
                for (int j = 0; j < 2; j++)
                    wmma::mma_sync(acc[i][j], af[i], bf[j], acc[i][j]);
        }
        __syncthreads();
    }
    #pragma unroll
    for (int i = 0; i < 2; i++)
        #pragma unroll
        for (int j = 0; j < 2; j++)
            wmma::store_matrix_sync(C + (size_t)(m0 + wm * 32 + i * 16) * 512 + n0 + wn * 32 + j * 16,
                                    acc[i][j], 512, wmma::mem_row_major);
}

// Pi fp32 -> fp16 (halves gather traffic in k_user)
__global__ void k_cvtPi() {
    size_t idx = (size_t)blockIdx.x * blockDim.x + threadIdx.x;   // 8 elems each
    if (idx >= (size_t)IP * 512 / 8) return;
    const float4* src = (const float4*)g_Pi + idx * 2;
    float4 a = src[0], b = src[1];
    __half2 h0 = __floats2half2_rn(a.x, a.y);
    __half2 h1 = __floats2half2_rn(a.z, a.w);
    __half2 h2 = __floats2half2_rn(b.x, b.y);
    __half2 h3 = __floats2half2_rn(b.z, b.w);
    uint4 packed = {*(unsigned*)&h0, *(unsigned*)&h1, *(unsigned*)&h2, *(unsigned*)&h3};
    ((uint4*)g_Pih)[idx] = packed;
}

// offsets: warp-scan of deg + one global atomic per warp (order-free CSR base)
__global__ void k_offsets() {
    int u = blockIdx.x * blockDim.x + threadIdx.x;
    int lane = threadIdx.x & 31;
    int v = (u < UN) ? g_deg[u] : 0;
    int x = v;
    #pragma unroll
    for (int o = 1; o < 32; o <<= 1) {
        int y = __shfl_up_sync(0xffffffffu, x, o);
        if (lane >= o) x += y;
    }
    int tot = __shfl_sync(0xffffffffu, x, 31);
    int base = 0;
    if (lane == 31) base = atomicAdd(&g_total, tot);
    base = __shfl_sync(0xffffffffu, base, 31);
    if (u < UN) g_off[u] = base + x - v;
}

// fused: dir0 wsum accumulation (8 threads/edge) + CSR fill (1 thread/edge)
__global__ void k_edgepost(const int* __restrict__ src_u, const int* __restrict__ dst_i) {
    int idx = blockIdx.x * blockDim.x + threadIdx.x;
    if (idx >= EN * 8) return;
    int e = idx >> 3, h = idx & 7;
    int s = src_u[e], d = dst_i[e];
    float v0 = g_uStat[s * 16 + h] + g_iStat[d * 16 + h];
    v0 = v0 > 0.f ? v0 : 0.2f * v0;
    float alpha = __expf(v0) / g_segsum0[d * 8 + h];
    atomicAdd(&g_wsum[s * 8 + h], alpha);
    if (h == 0) {
        int pos = g_off[s] + atomicAdd(&g_cursor[s], 1);
        g_epack[pos] = make_int2(e, d);
    }
}

// T[h,k] = sum_u wsum[u,h] * Hu[u,k]
__global__ void __launch_bounds__(128) k_T() {
    int t = threadIdx.x;
    int u0 = blockIdx.x * 128;
    int nit = (UN - u0 < 128) ? (UN - u0) : 128;
    float acc[8][4];
    #pragma unroll
    for (int h = 0; h < 8; h++)
        #pragma unroll
        for (int q = 0; q < 4; q++) acc[h][q] = 0.f;
    for (int i = 0; i < nit; i++) {
        int u = u0 + i;
        const float4* wp = (const float4*)(g_wsum + (size_t)u * 8);
        float4 wa = wp[0], wb = wp[1];
        float wv[8] = {wa.x, wa.y, wa.z, wa.w, wb.x, wb.y, wb.z, wb.w};
        uint2 hraw = *(const uint2*)(g_Hu + (size_t)u * 512 + t * 4);
        float2 x01 = __half22float2(*(__half2*)&hraw.x);
        float2 x23 = __half22float2(*(__half2*)&hraw.y);
        float xv[4] = {x01.x, x01.y, x23.x, x23.y};
        #pragma unroll
        for (int h = 0; h < 8; h++) {
            float w = wv[h];
            #pragma unroll
            for (int q = 0; q < 4; q++) acc[h][q] += w * xv[q];
        }
    }
    #pragma unroll
    for (int h = 0; h < 8; h++)
        #pragma unroll
        for (int q = 0; q < 4; q++)
            atomicAdd(&g_T[h * 512 + t * 4 + q], acc[h][q]);
}

// colsum[h*64+d] += sum_{k-chunk} T[h,k]*Wui[k, h*64+d]; grid (8 heads, 8 k-chunks)
__global__ void __launch_bounds__(64) k_smallgemm(const float* __restrict__ Wui) {
    int h = blockIdx.x, kc = blockIdx.y, d = threadIdx.x;
    int c = h * 64 + d;
    __shared__ float Ts[64];
    Ts[d] = g_T[h * 512 + kc * 64 + d];
    __syncthreads();
    float acc = 0.f;
    #pragma unroll 8
    for (int k = 0; k < 64; k++)
        acc += Ts[k] * Wui[(size_t)(kc * 64 + k) * 512 + c];
    atomicAdd(&g_colsum[c], acc);
}

// dir1 + final: one block per user; fp16 Pi gather; write 1024-wide row
__global__ void __launch_bounds__(128) k_user(float* __restrict__ out,
                                              const float* __restrict__ b_iu,
                                              const float* __restrict__ b_ui) {
    int d = blockIdx.x;
    int t = threadIdx.x;      // 128, owns cols 4t..4t+3
    int h = t >> 4;
    int off = g_off[d];
    int deg = g_deg[d];
    float sinv = 1.f / g_segsum1[d * 8 + h];
    float4 a = {0.f, 0.f, 0.f, 0.f};
    int j = 0;
    for (; j + 2 <= deg; j += 2) {
        int2 p0 = g_epack[off + j], p1 = g_epack[off + j + 1];
        float w0 = g_ebuf1[(size_t)p0.x * 8 + h] * sinv;
        float w1 = g_ebuf1[(size_t)p1.x * 8 + h] * sinv;
        uint2 r0 = *(const uint2*)(g_Pih + (size_t)p0.y * 512 + t * 4);
        uint2 r1 = *(const uint2*)(g_Pih + (size_t)p1.y * 512 + t * 4);
        float2 q0a = __half22float2(*(__half2*)&r0.x), q0b = __half22float2(*(__half2*)&r0.y);
        float2 q1a = __half22float2(*(__half2*)&r1.x), q1b = __half22float2(*(__half2*)&r1.y);
        a.x += q0a.x * w0 + q1a.x * w1;
        a.y += q0a.y * w0 + q1a.y * w1;
        a.z += q0b.x * w0 + q1b.x * w1;
        a.w += q0b.y * w0 + q1b.y * w1;
    }
    if (j < deg) {
        int2 p0 = g_epack[off + j];
        float w0 = g_ebuf1[(size_t)p0.x * 8 + h] * sinv;
        uint2 r0 = *(const uint2*)(g_Pih + (size_t)p0.y * 512 + t * 4);
        float2 q0a = __half22float2(*(__half2*)&r0.x), q0b = __half22float2(*(__half2*)&r0.y);
        a.x += q0a.x * w0; a.y += q0a.y * w0; a.z += q0b.x * w0; a.w += q0b.y * w0;
    }
    float4 b0 = ((const float4*)b_iu)[t];
    ((float4*)(out + (size_t)d * 1024))[t] =
        make_float4(a.x + b0.x, a.y + b0.y, a.z + b0.z, a.w + b0.w);
    float4 cs = ((const float4*)g_colsum)[t];
    float4 b1 = ((const float4*)b_ui)[t];
    const float inv = 1.f / IN_;
    ((float4*)(out + (size_t)d * 1024 + 512))[t] =
        make_float4(cs.x * inv + b1.x, cs.y * inv + b1.y,
                    cs.z * inv + b1.z, cs.w * inv + b1.w);
}

// ---------------- launch ----------------
extern "C" void kernel_launch(void* const* d_in, const int* in_sizes, int n_in,
                              void* d_out, int out_size) {
    (void)in_sizes; (void)n_in; (void)out_size;
    const int*   u_gid    = (const int*)  d_in[0];
    const int*   i_gid    = (const int*)  d_in[1];
    const int*   src_u    = (const int*)  d_in[2];
    const int*   dst_i    = (const int*)  d_in[3];
    const float* user_emb = (const float*)d_in[4];
    const float* item_emb = (const float*)d_in[5];
    const float* W_ui     = (const float*)d_in[6];
    const float* al_ui    = (const float*)d_in[7];
    const float* ar_ui    = (const float*)d_in[8];
    const float* b_ui     = (const float*)d_in[9];
    const float* W_iu     = (const float*)d_in[10];
    const float* al_iu    = (const float*)d_in[11];
    const float* ar_iu    = (const float*)d_in[12];
    const float* b_iu     = (const float*)d_in[13];
    float* out = (float*)d_out;

    k_zero<<<(UN * 8 + 255) / 256, 256>>>();                                      // 1
    k_prep<<<(512 * 512 + 255) / 256, 256>>>(W_ui, W_iu, al_ui, ar_ui, al_iu, ar_iu); // 2
    k_stat<<<UB + IB, 256>>>(user_emb, item_emb, u_gid, i_gid);                   // 3
    k_edge_all<<<(EN * 8 + 255) / 256, 256>>>(src_u, dst_i);                      // 4
    k_gemm<<<dim3(IP / 128, 8), 256>>>();                                         // 5
    k_cvtPi<<<((IP * 512 / 8) + 255) / 256, 256>>>();                             // 6
    k_offsets<<<(UN + 255) / 256, 256>>>();                                       // 7
    k_edgepost<<<(EN * 8 + 255) / 256, 256>>>(src_u, dst_i);                      // 8
    k_T<<<(UN + 127) / 128, 128>>>();                                             // 9
    k_smallgemm<<<dim3(8, 8), 64>>>(W_ui);                                        // 10
    k_user<<<UN, 128>>>(out, b_iu, b_ui);                                         // 11
}

// round 13
// speedup vs baseline: 6.2647x; 1.4421x over previous
#include <cuda_runtime.h>
#include <cuda_fp16.h>
#include <mma.h>
#include <cstdint>

using namespace nvcuda;

#define UN   50000
#define IN_  20000
#define EN   400000
#define UP   50048
#define IP   20096   // 128-row padded

// ---------------- device scratch (BSS, no allocations) ----------------
__device__ __align__(16) __half g_Hu[(size_t)UP * 512];
__device__ __align__(16) __half g_Hi[(size_t)IP * 512];
__device__ __align__(16) __half g_Wh[512 * 512];          // W_iu fp16
__device__ __align__(16) __half g_Pih[(size_t)IP * 512];  // GEMM out, fp16
__device__ __align__(16) float  g_Mu[512 * 16];
__device__ __align__(16) float  g_Mi[512 * 16];
__device__ float  g_uStat[UN * 16];
__device__ float  g_iStat[IN_ * 16];
__device__ float  g_ebuf1[(size_t)EN * 8];
__device__ float  g_segsum0[IN_ * 8];
__device__ float  g_segsum1[UN * 8];
__device__ float  g_wsum[UN * 8];
__device__ float  g_T[8 * 512];
__device__ float  g_colsum[512];
__device__ int    g_deg[UN];
__device__ int    g_cursor[UN];
__device__ int    g_off[UN];
__device__ int    g_total;
__device__ __align__(8) int2 g_epack[EN];   // (edge id, src item)

// ---------------- helpers ----------------
__device__ __forceinline__ void cp_async16(void* s, const void* g) {
    asm volatile("cp.async.cg.shared.global [%0], [%1], 16;"
                 :: "r"((unsigned)__cvta_generic_to_shared(s)), "l"(g));
}
#define CP_COMMIT() asm volatile("cp.async.commit_group;")
#define CP_WAIT(n)  asm volatile("cp.async.wait_group %0;" :: "n"(n))

// ---------------- kernels ----------------
__global__ void k_zero() {
    int idx = blockIdx.x * blockDim.x + threadIdx.x;
    if (idx < UN * 8) { g_segsum1[idx] = 0.f; g_wsum[idx] = 0.f; }
    if (idx < IN_ * 8) g_segsum0[idx] = 0.f;
    if (idx < UN) { g_deg[idx] = 0; g_cursor[idx] = 0; }
    if (idx < 8 * 512) g_T[idx] = 0.f;
    if (idx < 512) g_colsum[idx] = 0.f;
    if (idx == 0) g_total = 0;
}

// Wh = fp16(W_iu);  fold (W, attn) into [512,16] projectors
__global__ void k_prep(const float* __restrict__ Wui, const float* __restrict__ Wiu,
                       const float* __restrict__ al_ui, const float* __restrict__ ar_ui,
                       const float* __restrict__ al_iu, const float* __restrict__ ar_iu) {
    int idx = blockIdx.x * blockDim.x + threadIdx.x;
    if (idx < 512 * 512) g_Wh[idx] = __float2half(Wiu[idx]);
    if (idx >= 512 * 16) return;
    int k = idx >> 4, j = idx & 15, h = j & 7;
    const float* W  = (j < 8) ? Wui   : Wiu;
    const float* au = (j < 8) ? al_ui : ar_iu;  // users
    const float* ai = (j < 8) ? ar_ui : al_iu;  // items
    const float4* wrow = (const float4*)(W + (size_t)k * 512 + h * 64);
    const float4* auv  = (const float4*)(au + h * 64);
    const float4* aiv  = (const float4*)(ai + h * 64);
    float su = 0.f, si = 0.f;
    #pragma unroll
    for (int q = 0; q < 16; q++) {
        float4 w = wrow[q], a = auv[q], b = aiv[q];
        su += w.x * a.x + w.y * a.y + w.z * a.z + w.w * a.w;
        si += w.x * b.x + w.y * b.y + w.z * b.z + w.w * b.w;
    }
    g_Mu[k * 16 + j] = su;
    g_Mi[k * 16 + j] = si;
}

// warp handles TWO rows: gather->fp16 + 16 attention stats; M loads amortized 2x
#define UB2 (UN / 16)   // 3125
#define IB2 (IN_ / 16)  // 1250
__global__ void __launch_bounds__(256) k_stat(const float* __restrict__ uemb,
                                              const float* __restrict__ iemb,
                                              const int* __restrict__ u_gid,
                                              const int* __restrict__ i_gid) {
    int w = threadIdx.x >> 5, lane = threadIdx.x & 31;
    int sel = (blockIdx.x >= UB2);
    int base = (sel ? (blockIdx.x - UB2) : blockIdx.x) * 16 + w * 2;
    const float* emb = sel ? iemb : uemb;
    const int* gid   = sel ? i_gid : u_gid;
    __half* H      = sel ? g_Hi   : g_Hu;
    const float* M = sel ? g_Mi   : g_Mu;
    float* stat    = sel ? g_iStat : g_uStat;

    const float4* x0 = (const float4*)(emb + (size_t)gid[base] * 512);
    const float4* x1 = (const float4*)(emb + (size_t)gid[base + 1] * 512);
    __half2* H0 = (__half2*)(H + (size_t)base * 512);
    __half2* H1 = (__half2*)(H + (size_t)(base + 1) * 512);

    float a0[16], a1[16];
    #pragma unroll
    for (int j = 0; j < 16; j++) { a0[j] = 0.f; a1[j] = 0.f; }

    #pragma unroll
    for (int q = 0; q < 4; q++) {
        int c4 = lane + 32 * q;
        float4 v0 = x0[c4], v1 = x1[c4];
        H0[c4 * 2]     = __floats2half2_rn(v0.x, v0.y);
        H0[c4 * 2 + 1] = __floats2half2_rn(v0.z, v0.w);
        H1[c4 * 2]     = __floats2half2_rn(v1.x, v1.y);
        H1[c4 * 2 + 1] = __floats2half2_rn(v1.z, v1.w);
        float xv0[4] = {v0.x, v0.y, v0.z, v0.w};
        float xv1[4] = {v1.x, v1.y, v1.z, v1.w};
        #pragma unroll
        for (int r = 0; r < 4; r++) {
            const float4* Mr = (const float4*)(M + (size_t)(c4 * 4 + r) * 16);
            float4 m0 = Mr[0], m1 = Mr[1], m2 = Mr[2], m3 = Mr[3];
            float s0 = xv0[r], s1 = xv1[r];
            a0[0] += s0 * m0.x;  a0[1] += s0 * m0.y;  a0[2] += s0 * m0.z;  a0[3] += s0 * m0.w;
            a0[4] += s0 * m1.x;  a0[5] += s0 * m1.y;  a0[6] += s0 * m1.z;  a0[7] += s0 * m1.w;
            a0[8] += s0 * m2.x;  a0[9] += s0 * m2.y;  a0[10] += s0 * m2.z; a0[11] += s0 * m2.w;
            a0[12] += s0 * m3.x; a0[13] += s0 * m3.y; a0[14] += s0 * m3.z; a0[15] += s0 * m3.w;
            a1[0] += s1 * m0.x;  a1[1] += s1 * m0.y;  a1[2] += s1 * m0.z;  a1[3] += s1 * m0.w;
            a1[4] += s1 * m1.x;  a1[5] += s1 * m1.y;  a1[6] += s1 * m1.z;  a1[7] += s1 * m1.w;
            a1[8] += s1 * m2.x;  a1[9] += s1 * m2.y;  a1[10] += s1 * m2.z; a1[11] += s1 * m2.w;
            a1[12] += s1 * m3.x; a1[13] += s1 * m3.y; a1[14] += s1 * m3.z; a1[15] += s1 * m3.w;
        }
    }
    #pragma unroll
    for (int j = 0; j < 16; j++) {
        #pragma unroll
        for (int o = 16; o >= 1; o >>= 1) {
            a0[j] += __shfl_xor_sync(0xffffffffu, a0[j], o);
            a1[j] += __shfl_xor_sync(0xffffffffu, a1[j], o);
        }
    }
    if (lane < 16) {
        stat[base * 16 + lane]       = a0[lane];
        stat[(base + 1) * 16 + lane] = a1[lane];
    }
}

// both directions fused: exp(leakyrelu(logit)), seg-sums, user degree
__global__ void k_edge_all(const int* __restrict__ src_u, const int* __restrict__ dst_i) {
    int idx = blockIdx.x * blockDim.x + threadIdx.x;
    if (idx >= EN * 8) return;
    int e = idx >> 3, h = idx & 7;
    int su = src_u[e], di = dst_i[e];
    float v0 = g_uStat[su * 16 + h] + g_iStat[di * 16 + h];
    v0 = v0 > 0.f ? v0 : 0.2f * v0;
    atomicAdd(&g_segsum0[di * 8 + h], __expf(v0));
    float v1 = g_iStat[di * 16 + 8 + h] + g_uStat[su * 16 + 8 + h];
    v1 = v1 > 0.f ? v1 : 0.2f * v1;
    float ex1 = __expf(v1);
    g_ebuf1[idx] = ex1;
    atomicAdd(&g_segsum1[su * 8 + h], ex1);
    if (h == 0) atomicAdd(&g_deg[su], 1);
}

// fp16 GEMM  Pih = fp16(Hi @ W_iu); BM=128 BN=64 BK=32, cp.async 2-stage,
// fp16 epilogue staged through per-warp smem (union-overlaid on As/Bs)
__global__ void __launch_bounds__(256) k_gemm() {
    const __half* A = g_Hi;
    const __half* B = g_Wh;

    __shared__ __align__(16) union SmemU {
        struct { __half As[2][128][40]; __half Bs[2][32][72]; } s;
        float Es[8][16][20];
    } su;

    int m0 = blockIdx.x * 128, n0 = blockIdx.y * 64;
    int tid = threadIdx.x;
    int warp = tid >> 5, lane = tid & 31;
    int wm = warp >> 1, wn = warp & 1;

    wmma::fragment<wmma::accumulator, 16, 16, 16, float> acc[2][2];
    #pragma unroll
    for (int i = 0; i < 2; i++)
        #pragma unroll
        for (int j = 0; j < 2; j++) wmma::fill_fragment(acc[i][j], 0.f);

    auto load_stage = [&](int st, int k0) {
        #pragma unroll
        for (int r = 0; r < 2; r++) {
            int v = tid * 2 + r;
            int row = v >> 2, col = (v & 3) * 8;
            cp_async16(&su.s.As[st][row][col], A + (size_t)(m0 + row) * 512 + k0 + col);
        }
        int brow = tid >> 3, bcol = (tid & 7) * 8;
        cp_async16(&su.s.Bs[st][brow][bcol], B + (size_t)(k0 + brow) * 512 + n0 + bcol);
    };

    load_stage(0, 0);
    CP_COMMIT();

    for (int k = 0; k < 16; k++) {
        if (k < 15) {
            load_stage((k + 1) & 1, (k + 1) * 32);
            CP_COMMIT();
            CP_WAIT(1);
        } else {
            CP_WAIT(0);
        }
        __syncthreads();
        int st = k & 1;
        #pragma unroll
        for (int ks = 0; ks < 2; ks++) {
            wmma::fragment<wmma::matrix_a, 16, 16, 16, __half, wmma::row_major> af[2];
            wmma::fragment<wmma::matrix_b, 16, 16, 16, __half, wmma::row_major> bf[2];
            #pragma unroll
            for (int i = 0; i < 2; i++)
                wmma::load_matrix_sync(af[i], &su.s.As[st][wm * 32 + i * 16][ks * 16], 40);
            #pragma unroll
            for (int j = 0; j < 2; j++)
                wmma::load_matrix_sync(bf[j], &su.s.Bs[st][ks * 16][wn * 32 + j * 16], 72);
            #pragma unroll
            for (int i = 0; i < 2; i++)
                #pragma unroll
                for (int j = 0; j < 2; j++)
                    wmma::mma_sync(acc[i][j], af[i], bf[j], acc[i][j]);
        }
        __syncthreads();
    }

    // fp16 epilogue: stage each 16x16 fp32 tile in per-warp smem, emit half2
    __syncthreads();   // all mma done before Es overlays As/Bs
    int row = lane >> 1, pb = (lane & 1) * 4;
    #pragma unroll
    for (int i = 0; i < 2; i++)
        #pragma unroll
        for (int j = 0; j < 2; j++) {
            wmma::store_matrix_sync(&su.Es[warp][0][0], acc[i][j], 20, wmma::mem_row_major);
            __syncwarp();
            __half2* dst = (__half2*)(g_Pih + (size_t)(m0 + wm * 32 + i * 16 + row) * 512
                                      + n0 + wn * 32 + j * 16);
            #pragma unroll
            for (int r = 0; r < 4; r++)
                dst[pb + r] = __floats2half2_rn(su.Es[warp][row][(pb + r) * 2],
                                                su.Es[warp][row][(pb + r) * 2 + 1]);
            __syncwarp();
        }
}

// offsets: warp-scan of deg + one global atomic per warp (order-free CSR base)
__global__ void k_offsets() {
    int u = blockIdx.x * blockDim.x + threadIdx.x;
    int lane = threadIdx.x & 31;
    int v = (u < UN) ? g_deg[u] : 0;
    int x = v;
    #pragma unroll
    for (int o = 1; o < 32; o <<= 1) {
        int y = __shfl_up_sync(0xffffffffu, x, o);
        if (lane >= o) x += y;
    }
    int tot = __shfl_sync(0xffffffffu, x, 31);
    int base = 0;
    if (lane == 31) base = atomicAdd(&g_total, tot);
    base = __shfl_sync(0xffffffffu, base, 31);
    if (u < UN) g_off[u] = base + x - v;
}

// fused: dir0 wsum accumulation (8 threads/edge) + CSR fill (1 thread/edge)
__global__ void k_edgepost(const int* __restrict__ src_u, const int* __restrict__ dst_i) {
    int idx = blockIdx.x * blockDim.x + threadIdx.x;
    if (idx >= EN * 8) return;
    int e = idx >> 3, h = idx & 7;
    int s = src_u[e], d = dst_i[e];
    float v0 = g_uStat[s * 16 + h] + g_iStat[d * 16 + h];
    v0 = v0 > 0.f ? v0 : 0.2f * v0;
    float alpha = __expf(v0) / g_segsum0[d * 8 + h];
    atomicAdd(&g_wsum[s * 8 + h], alpha);
    if (h == 0) {
        int pos = g_off[s] + atomicAdd(&g_cursor[s], 1);
        g_epack[pos] = make_int2(e, d);
    }
}

// T[h,k] = sum_u wsum[u,h] * Hu[u,k]
__global__ void __launch_bounds__(128) k_T() {
    int t = threadIdx.x;
    int u0 = blockIdx.x * 128;
    int nit = (UN - u0 < 128) ? (UN - u0) : 128;
    float acc[8][4];
    #pragma unroll
    for (int h = 0; h < 8; h++)
        #pragma unroll
        for (int q = 0; q < 4; q++) acc[h][q] = 0.f;
    for (int i = 0; i < nit; i++) {
        int u = u0 + i;
        const float4* wp = (const float4*)(g_wsum + (size_t)u * 8);
        float4 wa = wp[0], wb = wp[1];
        float wv[8] = {wa.x, wa.y, wa.z, wa.w, wb.x, wb.y, wb.z, wb.w};
        uint2 hraw = *(const uint2*)(g_Hu + (size_t)u * 512 + t * 4);
        float2 x01 = __half22float2(*(__half2*)&hraw.x);
        float2 x23 = __half22float2(*(__half2*)&hraw.y);
        float xv[4] = {x01.x, x01.y, x23.x, x23.y};
        #pragma unroll
        for (int h = 0; h < 8; h++) {
            float w = wv[h];
            #pragma unroll
            for (int q = 0; q < 4; q++) acc[h][q] += w * xv[q];
        }
    }
    #pragma unroll
    for (int h = 0; h < 8; h++)
        #pragma unroll
        for (int q = 0; q < 4; q++)
            atomicAdd(&g_T[h * 512 + t * 4 + q], acc[h][q]);
}

// colsum[h*64+d] += sum_{k-chunk} T[h,k]*Wui[k, h*64+d]; grid (8 heads, 8 k-chunks)
__global__ void __launch_bounds__(64) k_smallgemm(const float* __restrict__ Wui) {
    int h = blockIdx.x, kc = blockIdx.y, d = threadIdx.x;
    int c = h * 64 + d;
    __shared__ float Ts[64];
    Ts[d] = g_T[h * 512 + kc * 64 + d];
    __syncthreads();
    float acc = 0.f;
    #pragma unroll 8
    for (int k = 0; k < 64; k++)
        acc += Ts[k] * Wui[(size_t)(kc * 64 + k) * 512 + c];
    atomicAdd(&g_colsum[c], acc);
}

// dir1 + final: one block per user; fp16 Pi gather; write 1024-wide row
__global__ void __launch_bounds__(128) k_user(float* __restrict__ out,
                                              const float* __restrict__ b_iu,
                                              const float* __restrict__ b_ui) {
    int d = blockIdx.x;
    int t = threadIdx.x;      // 128, owns cols 4t..4t+3
    int h = t >> 4;
    int off = g_off[d];
    int deg = g_deg[d];
    float sinv = 1.f / g_segsum1[d * 8 + h];
    float4 a = {0.f, 0.f, 0.f, 0.f};
    int j = 0;
    for (; j + 2 <= deg; j += 2) {
        int2 p0 = g_epack[off + j], p1 = g_epack[off + j + 1];
        float w0 = g_ebuf1[(size_t)p0.x * 8 + h] * sinv;
        float w1 = g_ebuf1[(size_t)p1.x * 8 + h] * sinv;
        uint2 r0 = *(const uint2*)(g_Pih + (size_t)p0.y * 512 + t * 4);
        uint2 r1 = *(const uint2*)(g_Pih + (size_t)p1.y * 512 + t * 4);
        float2 q0a = __half22float2(*(__half2*)&r0.x), q0b = __half22float2(*(__half2*)&r0.y);
        float2 q1a = __half22float2(*(__half2*)&r1.x), q1b = __half22float2(*(__half2*)&r1.y);
        a.x += q0a.x * w0 + q1a.x * w1;
        a.y += q0a.y * w0 + q1a.y * w1;
        a.z += q0b.x * w0 + q1b.x * w1;
        a.w += q0b.y * w0 + q1b.y * w1;
    }
    if (j < deg) {
        int2 p0 = g_epack[off + j];
        float w0 = g_ebuf1[(size_t)p0.x * 8 + h] * sinv;
        uint2 r0 = *(const uint2*)(g_Pih + (size_t)p0.y * 512 + t * 4);
        float2 q0a = __half22float2(*(__half2*)&r0.x), q0b = __half22float2(*(__half2*)&r0.y);
        a.x += q0a.x * w0; a.y += q0a.y * w0; a.z += q0b.x * w0; a.w += q0b.y * w0;
    }
    float4 b0 = ((const float4*)b_iu)[t];
    ((float4*)(out + (size_t)d * 1024))[t] =
        make_float4(a.x + b0.x, a.y + b0.y, a.z + b0.z, a.w + b0.w);
    float4 cs = ((const float4*)g_colsum)[t];
    float4 b1 = ((const float4*)b_ui)[t];
    const float inv = 1.f / IN_;
    ((float4*)(out + (size_t)d * 1024 + 512))[t] =
        make_float4(cs.x * inv + b1.x, cs.y * inv + b1.y,
                    cs.z * inv + b1.z, cs.w * inv + b1.w);
}

// ---------------- launch ----------------
extern "C" void kernel_launch(void* const* d_in, const int* in_sizes, int n_in,
                              void* d_out, int out_size) {
    (void)in_sizes; (void)n_in; (void)out_size;
    const int*   u_gid    = (const int*)  d_in[0];
    const int*   i_gid    = (const int*)  d_in[1];
    const int*   src_u    = (const int*)  d_in[2];
    const int*   dst_i    = (const int*)  d_in[3];
    const float* user_emb = (const float*)d_in[4];
    const float* item_emb = (const float*)d_in[5];
    const float* W_ui     = (const float*)d_in[6];
    const float* al_ui    = (const float*)d_in[7];
    const float* ar_ui    = (const float*)d_in[8];
    const float* b_ui     = (const float*)d_in[9];
    const float* W_iu     = (const float*)d_in[10];
    const float* al_iu    = (const float*)d_in[11];
    const float* ar_iu    = (const float*)d_in[12];
    const float* b_iu     = (const float*)d_in[13];
    float* out = (float*)d_out;

    k_zero<<<(UN * 8 + 255) / 256, 256>>>();                                      // 1
    k_prep<<<(512 * 512 + 255) / 256, 256>>>(W_ui, W_iu, al_ui, ar_ui, al_iu, ar_iu); // 2
    k_stat<<<UB2 + IB2, 256>>>(user_emb, item_emb, u_gid, i_gid);                 // 3
    k_edge_all<<<(EN * 8 + 255) / 256, 256>>>(src_u, dst_i);                      // 4 <- ncu slot
    k_gemm<<<dim3(IP / 128, 8), 256>>>();                                         // 5
    k_offsets<<<(UN + 255) / 256, 256>>>();                                       // 6
    k_edgepost<<<(EN * 8 + 255) / 256, 256>>>(src_u, dst_i);                      // 7
    k_T<<<(UN + 127) / 128, 128>>>();                                             // 8
    k_smallgemm<<<dim3(8, 8), 64>>>(W_ui);                                        // 9
    k_user<<<UN, 128>>>(out, b_iu, b_ui);                                         // 10
}

// round 14
// speedup vs baseline: 6.4424x; 1.0284x over previous
#include <cuda_runtime.h>
#include <cuda_fp16.h>
#include <mma.h>
#include <cstdint>

using namespace nvcuda;

#define UN   50000
#define IN_  20000
#define EN   400000
#define UP   50048
#define IP   20096   // 128-row padded

// ---------------- device scratch (BSS, no allocations) ----------------
__device__ __align__(16) __half g_Hu[(size_t)UP * 512];
__device__ __align__(16) __half g_Hi[(size_t)IP * 512];
__device__ __align__(16) __half g_Wh[512 * 512];          // W_iu fp16
__device__ __align__(16) __half g_Pih[(size_t)IP * 512];  // GEMM out, fp16
__device__ __align__(16) float  g_Mu[512 * 16];
__device__ __align__(16) float  g_Mi[512 * 16];
__device__ float  g_uStat[UN * 16];
__device__ float  g_iStat[IN_ * 16];
__device__ float  g_ebuf1[(size_t)EN * 8];
__device__ float  g_segsum0[IN_ * 8];
__device__ float  g_segsum1[UN * 8];
__device__ float  g_wsum[UN * 8];
__device__ float  g_T[8 * 512];
__device__ float  g_colsum[512];
__device__ int    g_deg[UN];
__device__ int    g_cursor[UN];
__device__ int    g_off[UN];
__device__ int    g_total;
__device__ __align__(8) int2 g_epack[EN];   // (edge id, src item)

// ---------------- helpers ----------------
__device__ __forceinline__ void cp_async16(void* s, const void* g) {
    asm volatile("cp.async.cg.shared.global [%0], [%1], 16;"
                 :: "r"((unsigned)__cvta_generic_to_shared(s)), "l"(g));
}
#define CP_COMMIT() asm volatile("cp.async.commit_group;")
#define CP_WAIT(n)  asm volatile("cp.async.wait_group %0;" :: "n"(n))

// ---------------- kernels ----------------
// fused: zero all accumulators + Wh=fp16(W_iu) + fold (W,attn) into projectors
__global__ void k_zeroprep(const float* __restrict__ Wui, const float* __restrict__ Wiu,
                           const float* __restrict__ al_ui, const float* __restrict__ ar_ui,
                           const float* __restrict__ al_iu, const float* __restrict__ ar_iu) {
    int idx = blockIdx.x * blockDim.x + threadIdx.x;
    if (idx < UN * 8) { g_segsum1[idx] = 0.f; g_wsum[idx] = 0.f; }
    if (idx < IN_ * 8) g_segsum0[idx] = 0.f;
    if (idx < UN) { g_deg[idx] = 0; g_cursor[idx] = 0; }
    if (idx < 8 * 512) g_T[idx] = 0.f;
    if (idx < 512) g_colsum[idx] = 0.f;
    if (idx == 0) g_total = 0;
    if (idx < 512 * 512) g_Wh[idx] = __float2half(Wiu[idx]);
    if (idx >= 512 * 16) return;
    int k = idx >> 4, j = idx & 15, h = j & 7;
    const float* W  = (j < 8) ? Wui   : Wiu;
    const float* au = (j < 8) ? al_ui : ar_iu;  // users
    const float* ai = (j < 8) ? ar_ui : al_iu;  // items
    const float4* wrow = (const float4*)(W + (size_t)k * 512 + h * 64);
    const float4* auv  = (const float4*)(au + h * 64);
    const float4* aiv  = (const float4*)(ai + h * 64);
    float su = 0.f, si = 0.f;
    #pragma unroll
    for (int q = 0; q < 16; q++) {
        float4 w = wrow[q], a = auv[q], b = aiv[q];
        su += w.x * a.x + w.y * a.y + w.z * a.z + w.w * a.w;
        si += w.x * b.x + w.y * b.y + w.z * b.z + w.w * b.w;
    }
    g_Mu[k * 16 + j] = su;
    g_Mi[k * 16 + j] = si;
}

// warp handles TWO rows: gather->fp16 + 16 attention stats (one node type)
__global__ void __launch_bounds__(256) k_stat2(const float* __restrict__ emb,
                                               const int* __restrict__ gid,
                                               int sel) {
    int w = threadIdx.x >> 5, lane = threadIdx.x & 31;
    int base = blockIdx.x * 16 + w * 2;
    __half* H      = sel ? g_Hi   : g_Hu;
    const float* M = sel ? g_Mi   : g_Mu;
    float* stat    = sel ? g_iStat : g_uStat;

    const float4* x0 = (const float4*)(emb + (size_t)gid[base] * 512);
    const float4* x1 = (const float4*)(emb + (size_t)gid[base + 1] * 512);
    __half2* H0 = (__half2*)(H + (size_t)base * 512);
    __half2* H1 = (__half2*)(H + (size_t)(base + 1) * 512);

    float a0[16], a1[16];
    #pragma unroll
    for (int j = 0; j < 16; j++) { a0[j] = 0.f; a1[j] = 0.f; }

    #pragma unroll
    for (int q = 0; q < 4; q++) {
        int c4 = lane + 32 * q;
        float4 v0 = x0[c4], v1 = x1[c4];
        H0[c4 * 2]     = __floats2half2_rn(v0.x, v0.y);
        H0[c4 * 2 + 1] = __floats2half2_rn(v0.z, v0.w);
        H1[c4 * 2]     = __floats2half2_rn(v1.x, v1.y);
        H1[c4 * 2 + 1] = __floats2half2_rn(v1.z, v1.w);
        float xv0[4] = {v0.x, v0.y, v0.z, v0.w};
        float xv1[4] = {v1.x, v1.y, v1.z, v1.w};
        #pragma unroll
        for (int r = 0; r < 4; r++) {
            const float4* Mr = (const float4*)(M + (size_t)(c4 * 4 + r) * 16);
            float4 m0 = Mr[0], m1 = Mr[1], m2 = Mr[2], m3 = Mr[3];
            float s0 = xv0[r], s1 = xv1[r];
            a0[0] += s0 * m0.x;  a0[1] += s0 * m0.y;  a0[2] += s0 * m0.z;  a0[3] += s0 * m0.w;
            a0[4] += s0 * m1.x;  a0[5] += s0 * m1.y;  a0[6] += s0 * m1.z;  a0[7] += s0 * m1.w;
            a0[8] += s0 * m2.x;  a0[9] += s0 * m2.y;  a0[10] += s0 * m2.z; a0[11] += s0 * m2.w;
            a0[12] += s0 * m3.x; a0[13] += s0 * m3.y; a0[14] += s0 * m3.z; a0[15] += s0 * m3.w;
            a1[0] += s1 * m0.x;  a1[1] += s1 * m0.y;  a1[2] += s1 * m0.z;  a1[3] += s1 * m0.w;
            a1[4] += s1 * m1.x;  a1[5] += s1 * m1.y;  a1[6] += s1 * m1.z;  a1[7] += s1 * m1.w;
            a1[8] += s1 * m2.x;  a1[9] += s1 * m2.y;  a1[10] += s1 * m2.z; a1[11] += s1 * m2.w;
            a1[12] += s1 * m3.x; a1[13] += s1 * m3.y; a1[14] += s1 * m3.z; a1[15] += s1 * m3.w;
        }
    }
    #pragma unroll
    for (int j = 0; j < 16; j++) {
        #pragma unroll
        for (int o = 16; o >= 1; o >>= 1) {
            a0[j] += __shfl_xor_sync(0xffffffffu, a0[j], o);
            a1[j] += __shfl_xor_sync(0xffffffffu, a1[j], o);
        }
    }
    if (lane < 16) {
        stat[base * 16 + lane]       = a0[lane];
        stat[(base + 1) * 16 + lane] = a1[lane];
    }
}

// both directions fused: exp(leakyrelu(logit)), seg-sums, user degree
__global__ void k_edge_all(const int* __restrict__ src_u, const int* __restrict__ dst_i) {
    int idx = blockIdx.x * blockDim.x + threadIdx.x;
    if (idx >= EN * 8) return;
    int e = idx >> 3, h = idx & 7;
    int su = src_u[e], di = dst_i[e];
    float v0 = g_uStat[su * 16 + h] + g_iStat[di * 16 + h];
    v0 = v0 > 0.f ? v0 : 0.2f * v0;
    atomicAdd(&g_segsum0[di * 8 + h], __expf(v0));
    float v1 = g_iStat[di * 16 + 8 + h] + g_uStat[su * 16 + 8 + h];
    v1 = v1 > 0.f ? v1 : 0.2f * v1;
    float ex1 = __expf(v1);
    g_ebuf1[idx] = ex1;
    atomicAdd(&g_segsum1[su * 8 + h], ex1);
    if (h == 0) atomicAdd(&g_deg[su], 1);
}

// fp16 GEMM  Pih = fp16(Hi @ W_iu); BM=128 BN=64 BK=32, cp.async 2-stage,
// fp16 epilogue staged through per-warp smem (union-overlaid on As/Bs)
__global__ void __launch_bounds__(256) k_gemm() {
    const __half* A = g_Hi;
    const __half* B = g_Wh;

    __shared__ __align__(16) union SmemU {
        struct { __half As[2][128][40]; __half Bs[2][32][72]; } s;
        float Es[8][16][20];
    } su;

    int m0 = blockIdx.x * 128, n0 = blockIdx.y * 64;
    int tid = threadIdx.x;
    int warp = tid >> 5, lane = tid & 31;
    int wm = warp >> 1, wn = warp & 1;

    wmma::fragment<wmma::accumulator, 16, 16, 16, float> acc[2][2];
    #pragma unroll
    for (int i = 0; i < 2; i++)
        #pragma unroll
        for (int j = 0; j < 2; j++) wmma::fill_fragment(acc[i][j], 0.f);

    auto load_stage = [&](int st, int k0) {
        #pragma unroll
        for (int r = 0; r < 2; r++) {
            int v = tid * 2 + r;
            int row = v >> 2, col = (v & 3) * 8;
            cp_async16(&su.s.As[st][row][col], A + (size_t)(m0 + row) * 512 + k0 + col);
        }
        int brow = tid >> 3, bcol = (tid & 7) * 8;
        cp_async16(&su.s.Bs[st][brow][bcol], B + (size_t)(k0 + brow) * 512 + n0 + bcol);
    };

    load_stage(0, 0);
    CP_COMMIT();

    for (int k = 0; k < 16; k++) {
        if (k < 15) {
            load_stage((k + 1) & 1, (k + 1) * 32);
            CP_COMMIT();
            CP_WAIT(1);
        } else {
            CP_WAIT(0);
        }
        __syncthreads();
        int st = k & 1;
        #pragma unroll
        for (int ks = 0; ks < 2; ks++) {
            wmma::fragment<wmma::matrix_a, 16, 16, 16, __half, wmma::row_major> af[2];
            wmma::fragment<wmma::matrix_b, 16, 16, 16, __half, wmma::row_major> bf[2];
            #pragma unroll
            for (int i = 0; i < 2; i++)
                wmma::load_matrix_sync(af[i], &su.s.As[st][wm * 32 + i * 16][ks * 16], 40);
            #pragma unroll
            for (int j = 0; j < 2; j++)
                wmma::load_matrix_sync(bf[j], &su.s.Bs[st][ks * 16][wn * 32 + j * 16], 72);
            #pragma unroll
            for (int i = 0; i < 2; i++)
                #pragma unroll
                for (int j = 0; j < 2; j++)
                    wmma::mma_sync(acc[i][j], af[i], bf[j], acc[i][j]);
        }
        __syncthreads();
    }

    __syncthreads();   // all mma done before Es overlays As/Bs
    int row = lane >> 1, pb = (lane & 1) * 4;
    #pragma unroll
    for (int i = 0; i < 2; i++)
        #pragma unroll
        for (int j = 0; j < 2; j++) {
            wmma::store_matrix_sync(&su.Es[warp][0][0], acc[i][j], 20, wmma::mem_row_major);
            __syncwarp();
            __half2* dst = (__half2*)(g_Pih + (size_t)(m0 + wm * 32 + i * 16 + row) * 512
                                      + n0 + wn * 32 + j * 16);
            #pragma unroll
            for (int r = 0; r < 4; r++)
                dst[pb + r] = __floats2half2_rn(su.Es[warp][row][(pb + r) * 2],
                                                su.Es[warp][row][(pb + r) * 2 + 1]);
            __syncwarp();
        }
}

// offsets: warp-scan of deg + one global atomic per warp (order-free CSR base)
__global__ void k_offsets() {
    int u = blockIdx.x * blockDim.x + threadIdx.x;
    int lane = threadIdx.x & 31;
    int v = (u < UN) ? g_deg[u] : 0;
    int x = v;
    #pragma unroll
    for (int o = 1; o < 32; o <<= 1) {
        int y = __shfl_up_sync(0xffffffffu, x, o);
        if (lane >= o) x += y;
    }
    int tot = __shfl_sync(0xffffffffu, x, 31);
    int base = 0;
    if (lane == 31) base = atomicAdd(&g_total, tot);
    base = __shfl_sync(0xffffffffu, base, 31);
    if (u < UN) g_off[u] = base + x - v;
}

// fused: dir0 wsum accumulation (8 threads/edge) + CSR fill (1 thread/edge)
__global__ void k_edgepost(const int* __restrict__ src_u, const int* __restrict__ dst_i) {
    int idx = blockIdx.x * blockDim.x + threadIdx.x;
    if (idx >= EN * 8) return;
    int e = idx >> 3, h = idx & 7;
    int s = src_u[e], d = dst_i[e];
    float v0 = g_uStat[s * 16 + h] + g_iStat[d * 16 + h];
    v0 = v0 > 0.f ? v0 : 0.2f * v0;
    float alpha = __expf(v0) / g_segsum0[d * 8 + h];
    atomicAdd(&g_wsum[s * 8 + h], alpha);
    if (h == 0) {
        int pos = g_off[s] + atomicAdd(&g_cursor[s], 1);
        g_epack[pos] = make_int2(e, d);
    }
}

// T[h,k] = sum_u wsum[u,h] * Hu[u,k]
__global__ void __launch_bounds__(128) k_T() {
    int t = threadIdx.x;
    int u0 = blockIdx.x * 128;
    int nit = (UN - u0 < 128) ? (UN - u0) : 128;
    float acc[8][4];
    #pragma unroll
    for (int h = 0; h < 8; h++)
        #pragma unroll
        for (int q = 0; q < 4; q++) acc[h][q] = 0.f;
    for (int i = 0; i < nit; i++) {
        int u = u0 + i;
        const float4* wp = (const float4*)(g_wsum + (size_t)u * 8);
        float4 wa = wp[0], wb = wp[1];
        float wv[8] = {wa.x, wa.y, wa.z, wa.w, wb.x, wb.y, wb.z, wb.w};
        uint2 hraw = *(const uint2*)(g_Hu + (size_t)u * 512 + t * 4);
        float2 x01 = __half22float2(*(__half2*)&hraw.x);
        float2 x23 = __half22float2(*(__half2*)&hraw.y);
        float xv[4] = {x01.x, x01.y, x23.x, x23.y};
        #pragma unroll
        for (int h = 0; h < 8; h++) {
            float w = wv[h];
            #pragma unroll
            for (int q = 0; q < 4; q++) acc[h][q] += w * xv[q];
        }
    }
    #pragma unroll
    for (int h = 0; h < 8; h++)
        #pragma unroll
        for (int q = 0; q < 4; q++)
            atomicAdd(&g_T[h * 512 + t * 4 + q], acc[h][q]);
}

// colsum[h*64+d] += sum_{k-chunk} T[h,k]*Wui[k, h*64+d]; grid (8 heads, 8 k-chunks)
__global__ void __launch_bounds__(64) k_smallgemm(const float* __restrict__ Wui) {
    int h = blockIdx.x, kc = blockIdx.y, d = threadIdx.x;
    int c = h * 64 + d;
    __shared__ float Ts[64];
    Ts[d] = g_T[h * 512 + kc * 64 + d];
    __syncthreads();
    float acc = 0.f;
    #pragma unroll 8
    for (int k = 0; k < 64; k++)
        acc += Ts[k] * Wui[(size_t)(kc * 64 + k) * 512 + c];
    atomicAdd(&g_colsum[c], acc);
}

// dir1 + final: one block per user; fp16 Pi gather; write 1024-wide row
__global__ void __launch_bounds__(128) k_user(float* __restrict__ out,
                                              const float* __restrict__ b_iu,
                                              const float* __restrict__ b_ui) {
    int d = blockIdx.x;
    int t = threadIdx.x;      // 128, owns cols 4t..4t+3
    int h = t >> 4;
    int off = g_off[d];
    int deg = g_deg[d];
    float sinv = 1.f / g_segsum1[d * 8 + h];
    float4 a = {0.f, 0.f, 0.f, 0.f};
    int j = 0;
    for (; j + 2 <= deg; j += 2) {
        int2 p0 = g_epack[off + j], p1 = g_epack[off + j + 1];
        float w0 = g_ebuf1[(size_t)p0.x * 8 + h] * sinv;
        float w1 = g_ebuf1[(size_t)p1.x * 8 + h] * sinv;
        uint2 r0 = *(const uint2*)(g_Pih + (size_t)p0.y * 512 + t * 4);
        uint2 r1 = *(const uint2*)(g_Pih + (size_t)p1.y * 512 + t * 4);
        float2 q0a = __half22float2(*(__half2*)&r0.x), q0b = __half22float2(*(__half2*)&r0.y);
        float2 q1a = __half22float2(*(__half2*)&r1.x), q1b = __half22float2(*(__half2*)&r1.y);
        a.x += q0a.x * w0 + q1a.x * w1;
        a.y += q0a.y * w0 + q1a.y * w1;
        a.z += q0b.x * w0 + q1b.x * w1;
        a.w += q0b.y * w0 + q1b.y * w1;
    }
    if (j < deg) {
        int2 p0 = g_epack[off + j];
        float w0 = g_ebuf1[(size_t)p0.x * 8 + h] * sinv;
        uint2 r0 = *(const uint2*)(g_Pih + (size_t)p0.y * 512 + t * 4);
        float2 q0a = __half22float2(*(__half2*)&r0.x), q0b = __half22float2(*(__half2*)&r0.y);
        a.x += q0a.x * w0; a.y += q0a.y * w0; a.z += q0b.x * w0; a.w += q0b.y * w0;
    }
    float4 b0 = ((const float4*)b_iu)[t];
    ((float4*)(out + (size_t)d * 1024))[t] =
        make_float4(a.x + b0.x, a.y + b0.y, a.z + b0.z, a.w + b0.w);
    float4 cs = ((const float4*)g_colsum)[t];
    float4 b1 = ((const float4*)b_ui)[t];
    const float inv = 1.f / IN_;
    ((float4*)(out + (size_t)d * 1024 + 512))[t] =
        make_float4(cs.x * inv + b1.x, cs.y * inv + b1.y,
                    cs.z * inv + b1.z, cs.w * inv + b1.w);
}

// ---------------- launch ----------------
extern "C" void kernel_launch(void* const* d_in, const int* in_sizes, int n_in,
                              void* d_out, int out_size) {
    (void)in_sizes; (void)n_in; (void)out_size;
    const int*   u_gid    = (const int*)  d_in[0];
    const int*   i_gid    = (const int*)  d_in[1];
    const int*   src_u    = (const int*)  d_in[2];
    const int*   dst_i    = (const int*)  d_in[3];
    const float* user_emb = (const float*)d_in[4];
    const float* item_emb = (const float*)d_in[5];
    const float* W_ui     = (const float*)d_in[6];
    const float* al_ui    = (const float*)d_in[7];
    const float* ar_ui    = (const float*)d_in[8];
    const float* b_ui     = (const float*)d_in[9];
    const float* W_iu     = (const float*)d_in[10];
    const float* al_iu    = (const float*)d_in[11];
    const float* ar_iu    = (const float*)d_in[12];
    const float* b_iu     = (const float*)d_in[13];
    float* out = (float*)d_out;

    cudaStream_t s2;
    cudaStreamCreate(&s2);
    cudaEvent_t evFork, evJoin;
    cudaEventCreateWithFlags(&evFork, cudaEventDisableTiming);
    cudaEventCreateWithFlags(&evJoin, cudaEventDisableTiming);

    k_zeroprep<<<(UN * 8 + 255) / 256, 256>>>(W_ui, W_iu, al_ui, ar_ui, al_iu, ar_iu);
    k_stat2<<<IN_ / 16, 256>>>(item_emb, i_gid, 1);      // items first

    cudaEventRecord(evFork, 0);
    cudaStreamWaitEvent(s2, evFork, 0);
    k_gemm<<<dim3(IP / 128, 8), 256, 0, s2>>>();         // overlaps chain below

    k_stat2<<<UN / 16, 256>>>(user_emb, u_gid, 0);       // users
    k_edge_all<<<(EN * 8 + 255) / 256, 256>>>(src_u, dst_i);
    k_offsets<<<(UN + 255) / 256, 256>>>();
    k_edgepost<<<(EN * 8 + 255) / 256, 256>>>(src_u, dst_i);
    k_T<<<(UN + 127) / 128, 128>>>();
    k_smallgemm<<<dim3(8, 8), 64>>>(W_ui);

    cudaEventRecord(evJoin, s2);
    cudaStreamWaitEvent(0, evJoin, 0);
    k_user<<<UN, 128>>>(out, b_iu, b_ui);

    cudaEventDestroy(evFork);
    cudaEventDestroy(evJoin);
    cudaStreamDestroy(s2);
}